// round 13
// baseline (speedup 1.0000x reference)
#include <cuda_runtime.h>
#include <cuda_fp16.h>
#include <math.h>
#include <stdint.h>

#define NGn   50000
#define NDn   20000
#define HD    128
#define EGGn  800000
#define EGDAn 400000
#define ELABn 200000

// ---------------- scratch (static device allocations; no cudaMalloc) ----------------
__device__ float g_aggA[(size_t)NGn * HD];
__device__ float g_aggB[(size_t)NGn * HD];
__device__ float g_aggD[(size_t)NDn * HD];
__device__ float g_g1[(size_t)NGn * HD];
__device__ float g_d1[(size_t)NDn * HD];
__device__ float g_g2[(size_t)NGn * HD];
__device__ float g_d2[(size_t)NDn * HD];
// fp16 gather mirrors
__device__ __half g_hxg[(size_t)NGn * HD];
__device__ __half g_hxd[(size_t)NDn * HD];
__device__ __half g_hg1[(size_t)NGn * HD];
__device__ __half g_hd1[(size_t)NDn * HD];
__device__ __half g_hg2[(size_t)NGn * HD];
__device__ __half g_hd2[(size_t)NDn * HD];

__device__ float g_W1f[2 * 3 * HD * HD];
__device__ float g_W2f[2 * 3 * HD * HD];
__device__ float g_bf [2 * 3 * HD];
__device__ __half g_WXgT[2 * HD * HD], g_WAgT[2 * HD * HD], g_WRgT[2 * HD * HD];
__device__ __half g_WXdT[2 * HD * HD], g_WAdT[2 * HD * HD];
__device__ float g_Bg[2 * HD], g_Bd[2 * HD];

__device__ int g_cnt_gg[NGn], g_cnt_rev[NGn], g_cnt_gda[NDn];
__device__ int g_off_gg[NGn], g_off_rev[NGn], g_off_gda[NDn];
__device__ int g_cur_gg[NGn], g_cur_rev[NGn], g_cur_gda[NDn];
__device__ int g_csr_gg[EGGn], g_csr_rev[EGDAn], g_csr_gda[EGDAn];
__device__ int g_bsum[160];
__device__ float g_sum[2 * HD], g_ssq[2 * HD];
__device__ float g_bnA[2 * HD], g_bnB[2 * HD];

#define NBG 49
#define NBD 20
#define NBTOT (NBG + NBG + NBD)

// ---------------- selectors ---------------------------------------------------------
__device__ __forceinline__ int* cnt_of(int e) { return e == 0 ? g_cnt_gg : (e == 1 ? g_cnt_rev : g_cnt_gda); }
__device__ __forceinline__ int* off_of(int e) { return e == 0 ? g_off_gg : (e == 1 ? g_off_rev : g_off_gda); }
__device__ __forceinline__ int  ndst_of(int e){ return e == 2 ? NDn : NGn; }

// ---------------- small PTX helpers --------------------------------------------------
__device__ __forceinline__ uint32_t smem_u32(const void* p) {
    uint32_t a;
    asm("{ .reg .u64 t; cvta.to.shared.u64 t, %1; cvt.u32.u64 %0, t; }" : "=r"(a) : "l"(p));
    return a;
}
__device__ __forceinline__ void cp_async16(uint32_t dst, const void* src, int src_bytes) {
    asm volatile("cp.async.ca.shared.global [%0], [%1], 16, %2;"
                 :: "r"(dst), "l"(src), "r"(src_bytes) : "memory");
}
__device__ __forceinline__ void cp_commit() { asm volatile("cp.async.commit_group;" ::: "memory"); }
__device__ __forceinline__ void cp_wait1() { asm volatile("cp.async.wait_group 1;" ::: "memory"); }
__device__ __forceinline__ void cp_wait0() { asm volatile("cp.async.wait_group 0;" ::: "memory"); }

__device__ __forceinline__ void mma_f16(float* d, const uint32_t* a, const uint32_t* b) {
    asm volatile(
        "mma.sync.aligned.m16n8k16.row.col.f32.f16.f16.f32 "
        "{%0,%1,%2,%3}, {%4,%5,%6,%7}, {%8,%9}, {%0,%1,%2,%3};\n"
        : "+f"(d[0]), "+f"(d[1]), "+f"(d[2]), "+f"(d[3])
        : "r"(a[0]), "r"(a[1]), "r"(a[2]), "r"(a[3]), "r"(b[0]), "r"(b[1]));
}
__device__ __forceinline__ uint32_t packh2(float lo, float hi) {
    __half2 h = __floats2half2_rn(lo, hi);
    return *(uint32_t*)&h;
}

// ---------------- CSR build ---------------------------------------------------------
__global__ void hist_all_kernel(const int* __restrict__ gg_dst,
                                const int* __restrict__ gda_src,
                                const int* __restrict__ gda_dst) {
    int total = EGGn + 2 * EGDAn;
    for (int i = blockIdx.x * blockDim.x + threadIdx.x; i < total; i += gridDim.x * blockDim.x) {
        if (i < EGGn) atomicAdd(&g_cnt_gg[gg_dst[i]], 1);
        else if (i < EGGn + EGDAn) atomicAdd(&g_cnt_rev[gda_src[i - EGGn]], 1);
        else atomicAdd(&g_cnt_gda[gda_dst[i - EGGn - EGDAn]], 1);
    }
}

__device__ __forceinline__ void scan_map(int b, int& e, int& chunk) {
    if (b < NBG)          { e = 0; chunk = b; }
    else if (b < 2 * NBG) { e = 1; chunk = b - NBG; }
    else                  { e = 2; chunk = b - 2 * NBG; }
}

__global__ void scan_phase1() {
    int e, chunk; scan_map(blockIdx.x, e, chunk);
    const int* cnt = cnt_of(e);
    int n = ndst_of(e);
    int base = chunk * 1024;
    int s = 0;
    for (int i = threadIdx.x; i < 1024; i += 256) {
        int idx = base + i;
        if (idx < n) s += cnt[idx];
    }
    __shared__ int red[256];
    red[threadIdx.x] = s; __syncthreads();
    for (int d = 128; d > 0; d >>= 1) {
        if (threadIdx.x < d) red[threadIdx.x] += red[threadIdx.x + d];
        __syncthreads();
    }
    if (threadIdx.x == 0) g_bsum[blockIdx.x] = red[0];
}

// phase3 with built-in segment prefix (replaces the old phase2 kernel):
// g_bsum holds RAW per-chunk sums; each block reduces its own segment prefix.
__global__ void scan_phase3() {
    int e, chunk; scan_map(blockIdx.x, e, chunk);
    const int* cnt = cnt_of(e);
    int* off = off_of(e);
    int* cur = (e == 0) ? g_cur_gg : (e == 1 ? g_cur_rev : g_cur_gda);
    int n = ndst_of(e);
    int segbase = (e == 0) ? 0 : (e == 1 ? NBG : 2 * NBG);

    __shared__ int sPrefix;
    if (threadIdx.x < 32) {
        int lane = threadIdx.x;
        int s = 0;
        if (lane < chunk) s += g_bsum[segbase + lane];
        if (lane + 32 < chunk) s += g_bsum[segbase + lane + 32];
        #pragma unroll
        for (int d = 16; d > 0; d >>= 1)
            s += __shfl_xor_sync(0xffffffffu, s, d);
        if (lane == 0) sPrefix = s;
    }

    int base = chunk * 1024;
    int v[4]; int lsum = 0;
    int i0 = base + threadIdx.x * 4;
    #pragma unroll
    for (int j = 0; j < 4; j++) { v[j] = (i0 + j < n) ? cnt[i0 + j] : 0; lsum += v[j]; }
    __shared__ int ps[256];
    ps[threadIdx.x] = lsum; __syncthreads();
    for (int d = 1; d < 256; d <<= 1) {
        int t = (threadIdx.x >= d) ? ps[threadIdx.x - d] : 0;
        __syncthreads();
        ps[threadIdx.x] += t;
        __syncthreads();
    }
    int run = sPrefix + ps[threadIdx.x] - lsum;
    #pragma unroll
    for (int j = 0; j < 4; j++) {
        if (i0 + j < n) { off[i0 + j] = run; cur[i0 + j] = run; }
        run += v[j];
    }
}

__global__ void fill_all_kernel(const int* __restrict__ gg_src, const int* __restrict__ gg_dst,
                                const int* __restrict__ gda_src, const int* __restrict__ gda_dst) {
    int total = EGGn + 2 * EGDAn;
    for (int i = blockIdx.x * blockDim.x + threadIdx.x; i < total; i += gridDim.x * blockDim.x) {
        if (i < EGGn) {
            int p = atomicAdd(&g_cur_gg[gg_dst[i]], 1);
            g_csr_gg[p] = gg_src[i];
        } else if (i < EGGn + EGDAn) {
            int j = i - EGGn;
            int p = atomicAdd(&g_cur_rev[gda_src[j]], 1);
            g_csr_rev[p] = gda_dst[j];
        } else {
            int j = i - EGGn - EGDAn;
            int p = atomicAdd(&g_cur_gda[gda_dst[j]], 1);
            g_csr_gda[p] = gda_src[j];
        }
    }
}

// ---------------- fp16 mirror of input features -------------------------------------
__global__ void tohalf_kernel(const float* __restrict__ xg, const float* __restrict__ xd) {
    size_t totalG = (size_t)NGn * HD / 4;
    size_t total = totalG + (size_t)NDn * HD / 4;
    for (size_t i = (size_t)blockIdx.x * blockDim.x + threadIdx.x; i < total;
         i += (size_t)gridDim.x * blockDim.x) {
        const float* src; __half* dst; size_t e;
        if (i < totalG) { src = xg; dst = g_hxg; e = i * 4; }
        else { src = xd; dst = g_hxd; e = (i - totalG) * 4; }
        float4 v = *(const float4*)(src + e);
        __half2 h0 = __floats2half2_rn(v.x, v.y);
        __half2 h1 = __floats2half2_rn(v.z, v.w);
        *(uint2*)(dst + e) = make_uint2(*(uint32_t*)&h0, *(uint32_t*)&h1);
    }
}

// ---------------- fused weight precompute -------------------------------------------
__global__ void wprep_kernel(const float* __restrict__ Wd1, const float* __restrict__ Ws1,
                             const float* __restrict__ Wu1, const float* __restrict__ Wd2,
                             const float* __restrict__ Ws2, const float* __restrict__ Wu2,
                             const float* __restrict__ bd1, const float* __restrict__ bs1,
                             const float* __restrict__ bu1, const float* __restrict__ bd2,
                             const float* __restrict__ bs2, const float* __restrict__ bu2) {
    int b = blockIdx.x;
    if (b < 48) {
        int l = b / 24, i = (b / 8) % 3, rc = b % 8;
        const float* Wd = (l ? Wd2 : Wd1) + i * HD * HD;
        const float* Ws = (l ? Ws2 : Ws1) + i * HD * HD;
        const float* Wu = (l ? Wu2 : Wu1) + i * 2 * HD * HD;
        int h  = threadIdx.x & 127;
        int dg = threadIdx.x >> 7;
        int d0 = rc * 16 + dg * 8;
        float a1[8], a2[8];
        #pragma unroll
        for (int r = 0; r < 8; r++) { a1[r] = 0.f; a2[r] = 0.f; }
        for (int k = 0; k < HD; k++) {
            float wt = Wu[k * HD + h];
            float wb = Wu[(k + HD) * HD + h];
            #pragma unroll
            for (int r = 0; r < 8; r++) {
                a1[r] += Wd[(d0 + r) * HD + k] * wt;
                a2[r] += Ws[(d0 + r) * HD + k] * wb;
            }
        }
        int base = (l * 3 + i) * HD * HD;
        #pragma unroll
        for (int r = 0; r < 8; r++) {
            g_W1f[base + (d0 + r) * HD + h] = a1[r];
            g_W2f[base + (d0 + r) * HD + h] = a2[r];
        }
    } else {
        int bb = b - 48;
        int l = bb / 3, i = bb % 3;
        if (threadIdx.x >= HD) return;
        const float* bd = (l ? bd2 : bd1) + i * HD;
        const float* bs = (l ? bs2 : bs1) + i * HD;
        const float* bu = (l ? bu2 : bu1) + i * HD;
        const float* Wu = (l ? Wu2 : Wu1) + i * 2 * HD * HD;
        int h = threadIdx.x;
        float acc = bu[h];
        for (int k = 0; k < HD; k++)
            acc += bd[k] * Wu[k * HD + h] + bs[k] * Wu[(k + HD) * HD + h];
        g_bf[(l * 3 + i) * HD + h] = acc;
    }
}

__global__ void wcombine_kernel() {
    int idx = blockIdx.x * blockDim.x + threadIdx.x;
    if (idx >= 2 * HD * HD) return;
    int l = idx / (HD * HD), r = idx % (HD * HD);
    int n = r >> 7, k = r & 127;
    int e = k * HD + n;
    int base = l * 3 * HD * HD;
    int o = l * HD * HD + n * HD + k;
    g_WXgT[o] = __float2half(0.5f * (g_W1f[base + e] + g_W1f[base + 2 * HD * HD + e]));
    g_WAgT[o] = __float2half(0.5f * g_W2f[base + e]);
    g_WRgT[o] = __float2half(0.5f * g_W2f[base + 2 * HD * HD + e]);
    g_WXdT[o] = __float2half(g_W1f[base + HD * HD + e]);
    g_WAdT[o] = __float2half(g_W2f[base + HD * HD + e]);
    if (r < HD) {
        g_Bg[l * HD + r] = 0.5f * (g_bf[l * 3 * HD + r] + g_bf[(l * 3 + 2) * HD + r]);
        g_Bd[l * HD + r] = g_bf[(l * 3 + 1) * HD + r];
    }
}

// ---------------- BN finalize -------------------------------------------------------
__global__ void bnfinal_kernel(const float* __restrict__ gamma, const float* __restrict__ beta) {
    int t = threadIdx.x;
    float inv_n = (t < HD) ? (1.0f / NGn) : (1.0f / NDn);
    float m = g_sum[t] * inv_n;
    float v = g_ssq[t] * inv_n - m * m;
    float a = rsqrtf(v + 1e-5f) * gamma[t];
    g_bnA[t] = a;
    g_bnB[t] = beta[t] - m * a;
}

// ---------------- mean aggregation (fp16 gather; 8B per lane per edge) --------------
__device__ __forceinline__ void acc_h4(float4& a, uint2 u) {
    float2 f0 = __half22float2(*(__half2*)&u.x);
    float2 f1 = __half22float2(*(__half2*)&u.y);
    a.x += f0.x; a.y += f0.y; a.z += f1.x; a.w += f1.y;
}
__device__ __forceinline__ void acc_h4_bn(float4& a, uint2 u, float4 av, float4 bv) {
    float2 f0 = __half22float2(*(__half2*)&u.x);
    float2 f1 = __half22float2(*(__half2*)&u.y);
    float x0 = fmaf(av.x, f0.x, bv.x); x0 = (x0 >= 0.f) ? x0 : 0.01f * x0;
    float x1 = fmaf(av.y, f0.y, bv.y); x1 = (x1 >= 0.f) ? x1 : 0.01f * x1;
    float x2 = fmaf(av.z, f1.x, bv.z); x2 = (x2 >= 0.f) ? x2 : 0.01f * x2;
    float x3 = fmaf(av.w, f1.y, bv.w); x3 = (x3 >= 0.f) ? x3 : 0.01f * x3;
    a.x += x0; a.y += x1; a.z += x2; a.w += x3;
}

__global__ void agg_all_kernel(int l) {
    int w = (blockIdx.x * blockDim.x + threadIdx.x) >> 5;
    int lane = threadIdx.x & 31;
    int etype, dst;
    if (w < NGn)                { etype = 0; dst = w; }
    else if (w < 2 * NGn)       { etype = 1; dst = w - NGn; }
    else if (w < 2 * NGn + NDn) { etype = 2; dst = w - 2 * NGn; }
    else return;

    const __half* __restrict__ xsrc;
    float* agg;
    const int* __restrict__ csr;
    int soff;
    if (etype == 0)      { xsrc = l ? g_hg1 : g_hxg; agg = g_aggA; csr = g_csr_gg;  soff = 0; }
    else if (etype == 1) { xsrc = l ? g_hd1 : g_hxd; agg = g_aggB; csr = g_csr_rev; soff = HD; }
    else                 { xsrc = l ? g_hg1 : g_hxg; agg = g_aggD; csr = g_csr_gda; soff = 0; }

    int o = off_of(etype)[dst];
    int c = cnt_of(etype)[dst];
    const int* __restrict__ p = csr + o;
    int coff = lane * 4;

    float4 av = make_float4(1.f, 1.f, 1.f, 1.f), bv = make_float4(0.f, 0.f, 0.f, 0.f);
    if (l) {
        av = *(const float4*)&g_bnA[soff + coff];
        bv = *(const float4*)&g_bnB[soff + coff];
    }

    float4 a0 = make_float4(0.f,0.f,0.f,0.f), a1 = a0, a2 = a0, a3 = a0;
    int j = 0;
    if (l) {
        for (; j + 4 <= c; j += 4) {
            uint2 u0 = *(const uint2*)(xsrc + (size_t)p[j]     * HD + coff);
            uint2 u1 = *(const uint2*)(xsrc + (size_t)p[j + 1] * HD + coff);
            uint2 u2 = *(const uint2*)(xsrc + (size_t)p[j + 2] * HD + coff);
            uint2 u3 = *(const uint2*)(xsrc + (size_t)p[j + 3] * HD + coff);
            acc_h4_bn(a0, u0, av, bv);
            acc_h4_bn(a1, u1, av, bv);
            acc_h4_bn(a2, u2, av, bv);
            acc_h4_bn(a3, u3, av, bv);
        }
        for (; j < c; j++) {
            uint2 u = *(const uint2*)(xsrc + (size_t)p[j] * HD + coff);
            acc_h4_bn(a0, u, av, bv);
        }
    } else {
        for (; j + 4 <= c; j += 4) {
            uint2 u0 = *(const uint2*)(xsrc + (size_t)p[j]     * HD + coff);
            uint2 u1 = *(const uint2*)(xsrc + (size_t)p[j + 1] * HD + coff);
            uint2 u2 = *(const uint2*)(xsrc + (size_t)p[j + 2] * HD + coff);
            uint2 u3 = *(const uint2*)(xsrc + (size_t)p[j + 3] * HD + coff);
            acc_h4(a0, u0);
            acc_h4(a1, u1);
            acc_h4(a2, u2);
            acc_h4(a3, u3);
        }
        for (; j < c; j++) {
            uint2 u = *(const uint2*)(xsrc + (size_t)p[j] * HD + coff);
            acc_h4(a0, u);
        }
    }
    a0.x += a1.x + a2.x + a3.x;
    a0.y += a1.y + a2.y + a3.y;
    a0.z += a1.z + a2.z + a3.z;
    a0.w += a1.w + a2.w + a3.w;
    float sc = 1.0f / fmaxf((float)c, 1.0f);
    a0.x *= sc; a0.y *= sc; a0.z *= sc; a0.w *= sc;
    *(float4*)(agg + (size_t)dst * HD + coff) = a0;
}

// ---------------- fp16 mma GEMM, cp.async double-buffered (R12-proven) --------------
#define PITCH 36
#define XBUF_WORDS (128 * PITCH)
#define WBUF_HALVES (128 * 40)
#define SA_WORD_OFF (2 * XBUF_WORDS + WBUF_HALVES)
#define GEMM_SMEM ((SA_WORD_OFF + 256) * 4)

__global__ __launch_bounds__(256) void gemm_async_kernel(const float* __restrict__ x_gene,
                                                         const float* __restrict__ x_dis,
                                                         int l, int nblkG) {
    extern __shared__ uint32_t smem[];
    uint32_t sbase = smem_u32(smem);
    uint32_t xs_base = sbase;
    uint32_t ws_base = sbase + 2 * XBUF_WORDS * 4;
    float (*Xsf)[128][PITCH] = (float(*)[128][PITCH])smem;
    __half* wsH = (__half*)(smem + 2 * XBUF_WORDS);
    float* sA = (float*)(smem + SA_WORD_OFF);
    float* sB = sA + 128;

    bool isG = blockIdx.x < (unsigned)nblkG;
    int nsrc = isG ? 3 : 2;
    int row0 = (isG ? blockIdx.x : (blockIdx.x - nblkG)) * 128;
    int nrows = isG ? NGn : NDn;
    int soff = isG ? 0 : HD;

    const float *X0, *X1, *X2 = nullptr;
    const __half *W0, *W1, *W2 = nullptr;
    const float* bias;
    float* out;
    __half* hmir;
    if (isG) {
        X0 = l ? g_g1 : x_gene; X1 = g_aggA; X2 = g_aggB;
        W0 = g_WXgT + l * HD * HD; W1 = g_WAgT + l * HD * HD; W2 = g_WRgT + l * HD * HD;
        bias = g_Bg + l * HD; out = l ? g_g2 : g_g1;
        hmir = l ? g_hg2 : g_hg1;
    } else {
        X0 = l ? g_d1 : x_dis; X1 = g_aggD;
        W0 = g_WXdT + l * HD * HD; W1 = g_WAdT + l * HD * HD;
        bias = g_Bd + l * HD; out = l ? g_d2 : g_d1;
        hmir = l ? g_hd2 : g_hd1;
    }

    int tid = threadIdx.x;
    int warp = tid >> 5, lane = tid & 31;
    int g = lane >> 2, tg = lane & 3;
    int rw = warp >> 1, cw = warp & 1;

    if (l && tid < 128) {
        sA[tid] = g_bnA[soff + tid];
        sB[tid] = g_bnB[soff + tid];
    }

    int xr = tid >> 3;
    int xq = (tid & 7) * 4;
    int wn = tid & 127;
    int wq = tid >> 7;

    int nch = nsrc * 4;

    auto stage = [&](int c, int buf) {
        int s = c >> 2, k0 = (c & 3) * 32;
        const float* Xp = (s == 0) ? X0 : ((s == 1) ? X1 : X2);
        const __half* Wp = (s == 0) ? W0 : ((s == 1) ? W1 : W2);
        #pragma unroll
        for (int i = 0; i < 4; i++) {
            int r = xr + i * 32;
            const float* src = Xp + (size_t)(row0 + r) * HD + k0 + xq;
            uint32_t dst = xs_base + (uint32_t)(buf * XBUF_WORDS + r * PITCH + xq) * 4;
            cp_async16(dst, src, (row0 + r < nrows) ? 16 : 0);
        }
        #pragma unroll
        for (int i = 0; i < 2; i++) {
            int q = wq + i * 2;
            const __half* src = Wp + (size_t)wn * HD + k0 + q * 8;
            uint32_t dst = ws_base + (uint32_t)(buf * WBUF_HALVES + wn * 40 + q * 8) * 2;
            cp_async16(dst, src, 16);
        }
        cp_commit();
    };

    float acc[2][8][4];
    #pragma unroll
    for (int mt = 0; mt < 2; mt++)
        #pragma unroll
        for (int nt = 0; nt < 8; nt++)
            #pragma unroll
            for (int i = 0; i < 4; i++) acc[mt][nt][i] = 0.f;

    stage(0, 0);
    stage(1, 1);

    for (int c = 0; c < nch; c++) {
        int buf = c & 1;
        if (c + 1 < nch) cp_wait1(); else cp_wait0();
        __syncthreads();

        bool bn = (l != 0) && (c < 4);
        int k0c = (c & 3) * 32;

        #pragma unroll
        for (int k16 = 0; k16 < 2; k16++) {
            int kb = k16 * 16;
            uint32_t b[8][2];
            #pragma unroll
            for (int nt = 0; nt < 8; nt++) {
                const __half* wr = wsH + buf * WBUF_HALVES + (cw * 64 + nt * 8 + g) * 40 + kb + 2 * tg;
                b[nt][0] = *(const uint32_t*)wr;
                b[nt][1] = *(const uint32_t*)(wr + 8);
            }
            float2 aaL, bbL, aaH, bbH;
            if (bn) {
                int c0 = k0c + kb + 2 * tg;
                aaL = *(const float2*)&sA[c0];     bbL = *(const float2*)&sB[c0];
                aaH = *(const float2*)&sA[c0 + 8]; bbH = *(const float2*)&sB[c0 + 8];
            }
            uint32_t a[2][4];
            #pragma unroll
            for (int mt = 0; mt < 2; mt++) {
                int rb = rw * 32 + mt * 16;
                float2 x0 = *(const float2*)&Xsf[buf][rb + g][kb + 2 * tg];
                float2 x1 = *(const float2*)&Xsf[buf][rb + g + 8][kb + 2 * tg];
                float2 x2 = *(const float2*)&Xsf[buf][rb + g][kb + 2 * tg + 8];
                float2 x3 = *(const float2*)&Xsf[buf][rb + g + 8][kb + 2 * tg + 8];
                if (bn) {
                    x0.x = fmaf(aaL.x, x0.x, bbL.x); x0.x = (x0.x >= 0.f) ? x0.x : 0.01f * x0.x;
                    x0.y = fmaf(aaL.y, x0.y, bbL.y); x0.y = (x0.y >= 0.f) ? x0.y : 0.01f * x0.y;
                    x1.x = fmaf(aaL.x, x1.x, bbL.x); x1.x = (x1.x >= 0.f) ? x1.x : 0.01f * x1.x;
                    x1.y = fmaf(aaL.y, x1.y, bbL.y); x1.y = (x1.y >= 0.f) ? x1.y : 0.01f * x1.y;
                    x2.x = fmaf(aaH.x, x2.x, bbH.x); x2.x = (x2.x >= 0.f) ? x2.x : 0.01f * x2.x;
                    x2.y = fmaf(aaH.y, x2.y, bbH.y); x2.y = (x2.y >= 0.f) ? x2.y : 0.01f * x2.y;
                    x3.x = fmaf(aaH.x, x3.x, bbH.x); x3.x = (x3.x >= 0.f) ? x3.x : 0.01f * x3.x;
                    x3.y = fmaf(aaH.y, x3.y, bbH.y); x3.y = (x3.y >= 0.f) ? x3.y : 0.01f * x3.y;
                }
                a[mt][0] = packh2(x0.x, x0.y);
                a[mt][1] = packh2(x1.x, x1.y);
                a[mt][2] = packh2(x2.x, x2.y);
                a[mt][3] = packh2(x3.x, x3.y);
            }
            #pragma unroll
            for (int mt = 0; mt < 2; mt++)
                #pragma unroll
                for (int nt = 0; nt < 8; nt++)
                    mma_f16(acc[mt][nt], a[mt], b[nt]);
        }
        __syncthreads();
        if (c + 2 < nch) stage(c + 2, buf);
    }

    // epilogue: bias add, store, fp16 mirror, layer-1 BN column stats
    bool do_stats = (l == 0);
    #pragma unroll
    for (int nt = 0; nt < 8; nt++) {
        int col = cw * 64 + nt * 8 + 2 * tg;
        float2 bv = *(const float2*)(bias + col);
        float s0 = 0.f, s1 = 0.f, q0 = 0.f, q1 = 0.f;
        #pragma unroll
        for (int mt = 0; mt < 2; mt++) {
            int r0 = row0 + rw * 32 + mt * 16 + g;
            if (r0 < nrows) {
                float y0 = acc[mt][nt][0] + bv.x;
                float y1 = acc[mt][nt][1] + bv.y;
                *(float2*)(out + (size_t)r0 * HD + col) = make_float2(y0, y1);
                *(uint32_t*)(hmir + (size_t)r0 * HD + col) = packh2(y0, y1);
                s0 += y0; s1 += y1; q0 += y0 * y0; q1 += y1 * y1;
            }
            int r1 = r0 + 8;
            if (r1 < nrows) {
                float y0 = acc[mt][nt][2] + bv.x;
                float y1 = acc[mt][nt][3] + bv.y;
                *(float2*)(out + (size_t)r1 * HD + col) = make_float2(y0, y1);
                *(uint32_t*)(hmir + (size_t)r1 * HD + col) = packh2(y0, y1);
                s0 += y0; s1 += y1; q0 += y0 * y0; q1 += y1 * y1;
            }
        }
        if (do_stats) {
            #pragma unroll
            for (int m = 4; m <= 16; m <<= 1) {
                s0 += __shfl_xor_sync(0xffffffffu, s0, m);
                s1 += __shfl_xor_sync(0xffffffffu, s1, m);
                q0 += __shfl_xor_sync(0xffffffffu, q0, m);
                q1 += __shfl_xor_sync(0xffffffffu, q1, m);
            }
            if (g == 0) {
                atomicAdd(&g_sum[soff + col], s0);
                atomicAdd(&g_sum[soff + col + 1], s1);
                atomicAdd(&g_ssq[soff + col], q0);
                atomicAdd(&g_ssq[soff + col + 1], q1);
            }
        }
    }
}

// ---------------- decoder (fp16 gather, fp32 dot) -----------------------------------
__global__ void decoder_kernel(const int* __restrict__ ls, const int* __restrict__ ld,
                               float* __restrict__ out, int n) {
    int e = (blockIdx.x * blockDim.x + threadIdx.x) >> 5;
    int lane = threadIdx.x & 31;
    if (e >= n) return;
    int a = ls[e], b = ld[e];
    uint2 uu = *(const uint2*)(g_hg2 + (size_t)a * HD + lane * 4);
    uint2 vv = *(const uint2*)(g_hd2 + (size_t)b * HD + lane * 4);
    float2 u0 = __half22float2(*(__half2*)&uu.x);
    float2 u1 = __half22float2(*(__half2*)&uu.y);
    float2 v0 = __half22float2(*(__half2*)&vv.x);
    float2 v1 = __half22float2(*(__half2*)&vv.y);
    float p = u0.x * v0.x + u0.y * v0.y + u1.x * v1.x + u1.y * v1.y;
    #pragma unroll
    for (int off = 16; off > 0; off >>= 1)
        p += __shfl_xor_sync(0xffffffffu, p, off);
    if (lane == 0) out[e] = p;
}

// ---------------- launch ------------------------------------------------------------
extern "C" void kernel_launch(void* const* d_in, const int* in_sizes, int n_in,
                              void* d_out, int out_size) {
    const float* x_gene  = (const float*)d_in[0];
    const float* x_dis   = (const float*)d_in[1];
    const float* W_dst1  = (const float*)d_in[2];
    const float* W_src1  = (const float*)d_in[3];
    const float* W_upd1  = (const float*)d_in[4];
    const float* b_dst1  = (const float*)d_in[5];
    const float* b_src1  = (const float*)d_in[6];
    const float* b_upd1  = (const float*)d_in[7];
    const float* W_dst2  = (const float*)d_in[8];
    const float* W_src2  = (const float*)d_in[9];
    const float* W_upd2  = (const float*)d_in[10];
    const float* b_dst2  = (const float*)d_in[11];
    const float* b_src2  = (const float*)d_in[12];
    const float* b_upd2  = (const float*)d_in[13];
    const float* bn_gamma = (const float*)d_in[14];
    const float* bn_beta  = (const float*)d_in[15];
    const int* gg_src  = (const int*)d_in[16];
    const int* gg_dst  = (const int*)d_in[17];
    const int* gda_src = (const int*)d_in[18];
    const int* gda_dst = (const int*)d_in[19];
    const int* label_src = (const int*)d_in[20];
    const int* label_dst = (const int*)d_in[21];
    float* out = (float*)d_out;

    cudaFuncSetAttribute(gemm_async_kernel, cudaFuncAttributeMaxDynamicSharedMemorySize, GEMM_SMEM);

    void *p_cnt_gg, *p_cnt_rev, *p_cnt_gda, *p_sum, *p_ssq;
    cudaGetSymbolAddress(&p_cnt_gg, g_cnt_gg);
    cudaGetSymbolAddress(&p_cnt_rev, g_cnt_rev);
    cudaGetSymbolAddress(&p_cnt_gda, g_cnt_gda);
    cudaGetSymbolAddress(&p_sum, g_sum);
    cudaGetSymbolAddress(&p_ssq, g_ssq);
    cudaMemsetAsync(p_cnt_gg, 0, NGn * sizeof(int));
    cudaMemsetAsync(p_cnt_rev, 0, NGn * sizeof(int));
    cudaMemsetAsync(p_cnt_gda, 0, NDn * sizeof(int));
    cudaMemsetAsync(p_sum, 0, 2 * HD * sizeof(float));
    cudaMemsetAsync(p_ssq, 0, 2 * HD * sizeof(float));

    // --- CSR build + fp16 input mirror ---
    hist_all_kernel<<<4096, 256>>>(gg_dst, gda_src, gda_dst);
    tohalf_kernel<<<2048, 256>>>(x_gene, x_dis);
    scan_phase1<<<NBTOT, 256>>>();
    scan_phase3<<<NBTOT, 256>>>();
    fill_all_kernel<<<4096, 256>>>(gg_src, gg_dst, gda_src, gda_dst);

    // --- fused weight precompute ---
    wprep_kernel<<<54, 256>>>(W_dst1, W_src1, W_upd1, W_dst2, W_src2, W_upd2,
                              b_dst1, b_src1, b_upd1, b_dst2, b_src2, b_upd2);
    wcombine_kernel<<<(2 * HD * HD + 255) / 256, 256>>>();

    const int aggWarps = 2 * NGn + NDn;
    const int aggBlk = (aggWarps * 32 + 255) / 256;
    const int nblkG = (NGn + 127) / 128;
    const int nblkD = (NDn + 127) / 128;

    for (int l = 0; l < 2; l++) {
        agg_all_kernel<<<aggBlk, 256>>>(l);
        gemm_async_kernel<<<nblkG + nblkD, 256, GEMM_SMEM>>>(x_gene, x_dis, l, nblkG);
        if (l == 0)
            bnfinal_kernel<<<1, 256>>>(bn_gamma, bn_beta);
    }

    decoder_kernel<<<(ELABn * 32 + 255) / 256, 256>>>(label_src, label_dst, out, ELABn);
}

// round 15
// speedup vs baseline: 1.0818x; 1.0818x over previous
#include <cuda_runtime.h>
#include <cuda_fp16.h>
#include <math.h>
#include <stdint.h>

#define NGn   50000
#define NDn   20000
#define HD    128
#define EGGn  800000
#define EGDAn 400000
#define ELABn 200000

// ---------------- scratch (static device allocations; no cudaMalloc) ----------------
__device__ float g_aggA[(size_t)NGn * HD];
__device__ float g_aggB[(size_t)NGn * HD];
__device__ float g_aggD[(size_t)NDn * HD];
__device__ float g_g1[(size_t)NGn * HD];
__device__ float g_d1[(size_t)NDn * HD];
__device__ float g_g2[(size_t)NGn * HD];
__device__ float g_d2[(size_t)NDn * HD];
// fp16 gather mirrors
__device__ __half g_hxg[(size_t)NGn * HD];
__device__ __half g_hxd[(size_t)NDn * HD];
__device__ __half g_hg1[(size_t)NGn * HD];
__device__ __half g_hd1[(size_t)NDn * HD];

__device__ float g_W1f[2 * 3 * HD * HD];
__device__ float g_W2f[2 * 3 * HD * HD];
__device__ float g_bf [2 * 3 * HD];
__device__ __half g_WXgT[2 * HD * HD], g_WAgT[2 * HD * HD], g_WRgT[2 * HD * HD];
__device__ __half g_WXdT[2 * HD * HD], g_WAdT[2 * HD * HD];
__device__ float g_Bg[2 * HD], g_Bd[2 * HD];

__device__ int g_cnt_gg[NGn], g_cnt_rev[NGn], g_cnt_gda[NDn];
__device__ int g_off_gg[NGn], g_off_rev[NGn], g_off_gda[NDn];
__device__ int g_cur_gg[NGn], g_cur_rev[NGn], g_cur_gda[NDn];
__device__ int g_csr_gg[EGGn], g_csr_rev[EGDAn], g_csr_gda[EGDAn];
__device__ int g_bsum[160];
__device__ float g_sum[2 * HD], g_ssq[2 * HD];
__device__ float g_bnA[2 * HD], g_bnB[2 * HD];

#define NBG 49
#define NBD 20
#define NBTOT (NBG + NBG + NBD)

// ---------------- selectors ---------------------------------------------------------
__device__ __forceinline__ int* cnt_of(int e) { return e == 0 ? g_cnt_gg : (e == 1 ? g_cnt_rev : g_cnt_gda); }
__device__ __forceinline__ int* off_of(int e) { return e == 0 ? g_off_gg : (e == 1 ? g_off_rev : g_off_gda); }
__device__ __forceinline__ int  ndst_of(int e){ return e == 2 ? NDn : NGn; }

// ---------------- small PTX helpers --------------------------------------------------
__device__ __forceinline__ uint32_t smem_u32(const void* p) {
    uint32_t a;
    asm("{ .reg .u64 t; cvta.to.shared.u64 t, %1; cvt.u32.u64 %0, t; }" : "=r"(a) : "l"(p));
    return a;
}
__device__ __forceinline__ void cp_async16(uint32_t dst, const void* src, int src_bytes) {
    asm volatile("cp.async.ca.shared.global [%0], [%1], 16, %2;"
                 :: "r"(dst), "l"(src), "r"(src_bytes) : "memory");
}
__device__ __forceinline__ void cp_commit() { asm volatile("cp.async.commit_group;" ::: "memory"); }
__device__ __forceinline__ void cp_wait1() { asm volatile("cp.async.wait_group 1;" ::: "memory"); }
__device__ __forceinline__ void cp_wait0() { asm volatile("cp.async.wait_group 0;" ::: "memory"); }

__device__ __forceinline__ void mma_f16(float* d, const uint32_t* a, const uint32_t* b) {
    asm volatile(
        "mma.sync.aligned.m16n8k16.row.col.f32.f16.f16.f32 "
        "{%0,%1,%2,%3}, {%4,%5,%6,%7}, {%8,%9}, {%0,%1,%2,%3};\n"
        : "+f"(d[0]), "+f"(d[1]), "+f"(d[2]), "+f"(d[3])
        : "r"(a[0]), "r"(a[1]), "r"(a[2]), "r"(a[3]), "r"(b[0]), "r"(b[1]));
}
__device__ __forceinline__ uint32_t packh2(float lo, float hi) {
    __half2 h = __floats2half2_rn(lo, hi);
    return *(uint32_t*)&h;
}

// ---------------- CSR build ---------------------------------------------------------
__global__ void hist_all_kernel(const int* __restrict__ gg_dst,
                                const int* __restrict__ gda_src,
                                const int* __restrict__ gda_dst) {
    int total = EGGn + 2 * EGDAn;
    for (int i = blockIdx.x * blockDim.x + threadIdx.x; i < total; i += gridDim.x * blockDim.x) {
        if (i < EGGn) atomicAdd(&g_cnt_gg[gg_dst[i]], 1);
        else if (i < EGGn + EGDAn) atomicAdd(&g_cnt_rev[gda_src[i - EGGn]], 1);
        else atomicAdd(&g_cnt_gda[gda_dst[i - EGGn - EGDAn]], 1);
    }
}

__device__ __forceinline__ void scan_map(int b, int& e, int& chunk) {
    if (b < NBG)          { e = 0; chunk = b; }
    else if (b < 2 * NBG) { e = 1; chunk = b - NBG; }
    else                  { e = 2; chunk = b - 2 * NBG; }
}

__global__ void scan_phase1() {
    int e, chunk; scan_map(blockIdx.x, e, chunk);
    const int* cnt = cnt_of(e);
    int n = ndst_of(e);
    int base = chunk * 1024;
    int s = 0;
    for (int i = threadIdx.x; i < 1024; i += 256) {
        int idx = base + i;
        if (idx < n) s += cnt[idx];
    }
    __shared__ int red[256];
    red[threadIdx.x] = s; __syncthreads();
    for (int d = 128; d > 0; d >>= 1) {
        if (threadIdx.x < d) red[threadIdx.x] += red[threadIdx.x + d];
        __syncthreads();
    }
    if (threadIdx.x == 0) g_bsum[blockIdx.x] = red[0];
}

// phase3 with built-in segment prefix (g_bsum holds RAW per-chunk sums)
__global__ void scan_phase3() {
    int e, chunk; scan_map(blockIdx.x, e, chunk);
    const int* cnt = cnt_of(e);
    int* off = off_of(e);
    int* cur = (e == 0) ? g_cur_gg : (e == 1 ? g_cur_rev : g_cur_gda);
    int n = ndst_of(e);
    int segbase = (e == 0) ? 0 : (e == 1 ? NBG : 2 * NBG);

    __shared__ int sPrefix;
    if (threadIdx.x < 32) {
        int lane = threadIdx.x;
        int s = 0;
        if (lane < chunk) s += g_bsum[segbase + lane];
        if (lane + 32 < chunk) s += g_bsum[segbase + lane + 32];
        #pragma unroll
        for (int d = 16; d > 0; d >>= 1)
            s += __shfl_xor_sync(0xffffffffu, s, d);
        if (lane == 0) sPrefix = s;
    }

    int base = chunk * 1024;
    int v[4]; int lsum = 0;
    int i0 = base + threadIdx.x * 4;
    #pragma unroll
    for (int j = 0; j < 4; j++) { v[j] = (i0 + j < n) ? cnt[i0 + j] : 0; lsum += v[j]; }
    __shared__ int ps[256];
    ps[threadIdx.x] = lsum; __syncthreads();
    for (int d = 1; d < 256; d <<= 1) {
        int t = (threadIdx.x >= d) ? ps[threadIdx.x - d] : 0;
        __syncthreads();
        ps[threadIdx.x] += t;
        __syncthreads();
    }
    int run = sPrefix + ps[threadIdx.x] - lsum;
    #pragma unroll
    for (int j = 0; j < 4; j++) {
        if (i0 + j < n) { off[i0 + j] = run; cur[i0 + j] = run; }
        run += v[j];
    }
}

__global__ void fill_all_kernel(const int* __restrict__ gg_src, const int* __restrict__ gg_dst,
                                const int* __restrict__ gda_src, const int* __restrict__ gda_dst) {
    int total = EGGn + 2 * EGDAn;
    for (int i = blockIdx.x * blockDim.x + threadIdx.x; i < total; i += gridDim.x * blockDim.x) {
        if (i < EGGn) {
            int p = atomicAdd(&g_cur_gg[gg_dst[i]], 1);
            g_csr_gg[p] = gg_src[i];
        } else if (i < EGGn + EGDAn) {
            int j = i - EGGn;
            int p = atomicAdd(&g_cur_rev[gda_src[j]], 1);
            g_csr_rev[p] = gda_dst[j];
        } else {
            int j = i - EGGn - EGDAn;
            int p = atomicAdd(&g_cur_gda[gda_dst[j]], 1);
            g_csr_gda[p] = gda_src[j];
        }
    }
}

// ---------------- fp16 mirror of input features -------------------------------------
__global__ void tohalf_kernel(const float* __restrict__ xg, const float* __restrict__ xd) {
    size_t totalG = (size_t)NGn * HD / 4;
    size_t total = totalG + (size_t)NDn * HD / 4;
    for (size_t i = (size_t)blockIdx.x * blockDim.x + threadIdx.x; i < total;
         i += (size_t)gridDim.x * blockDim.x) {
        const float* src; __half* dst; size_t e;
        if (i < totalG) { src = xg; dst = g_hxg; e = i * 4; }
        else { src = xd; dst = g_hxd; e = (i - totalG) * 4; }
        float4 v = *(const float4*)(src + e);
        __half2 h0 = __floats2half2_rn(v.x, v.y);
        __half2 h1 = __floats2half2_rn(v.z, v.w);
        *(uint2*)(dst + e) = make_uint2(*(uint32_t*)&h0, *(uint32_t*)&h1);
    }
}

// ---------------- fused weight precompute -------------------------------------------
__global__ void wprep_kernel(const float* __restrict__ Wd1, const float* __restrict__ Ws1,
                             const float* __restrict__ Wu1, const float* __restrict__ Wd2,
                             const float* __restrict__ Ws2, const float* __restrict__ Wu2,
                             const float* __restrict__ bd1, const float* __restrict__ bs1,
                             const float* __restrict__ bu1, const float* __restrict__ bd2,
                             const float* __restrict__ bs2, const float* __restrict__ bu2) {
    int b = blockIdx.x;
    if (b < 48) {
        int l = b / 24, i = (b / 8) % 3, rc = b % 8;
        const float* Wd = (l ? Wd2 : Wd1) + i * HD * HD;
        const float* Ws = (l ? Ws2 : Ws1) + i * HD * HD;
        const float* Wu = (l ? Wu2 : Wu1) + i * 2 * HD * HD;
        int h  = threadIdx.x & 127;
        int dg = threadIdx.x >> 7;
        int d0 = rc * 16 + dg * 8;
        float a1[8], a2[8];
        #pragma unroll
        for (int r = 0; r < 8; r++) { a1[r] = 0.f; a2[r] = 0.f; }
        for (int k = 0; k < HD; k++) {
            float wt = Wu[k * HD + h];
            float wb = Wu[(k + HD) * HD + h];
            #pragma unroll
            for (int r = 0; r < 8; r++) {
                a1[r] += Wd[(d0 + r) * HD + k] * wt;
                a2[r] += Ws[(d0 + r) * HD + k] * wb;
            }
        }
        int base = (l * 3 + i) * HD * HD;
        #pragma unroll
        for (int r = 0; r < 8; r++) {
            g_W1f[base + (d0 + r) * HD + h] = a1[r];
            g_W2f[base + (d0 + r) * HD + h] = a2[r];
        }
    } else {
        int bb = b - 48;
        int l = bb / 3, i = bb % 3;
        if (threadIdx.x >= HD) return;
        const float* bd = (l ? bd2 : bd1) + i * HD;
        const float* bs = (l ? bs2 : bs1) + i * HD;
        const float* bu = (l ? bu2 : bu1) + i * HD;
        const float* Wu = (l ? Wu2 : Wu1) + i * 2 * HD * HD;
        int h = threadIdx.x;
        float acc = bu[h];
        for (int k = 0; k < HD; k++)
            acc += bd[k] * Wu[k * HD + h] + bs[k] * Wu[(k + HD) * HD + h];
        g_bf[(l * 3 + i) * HD + h] = acc;
    }
}

__global__ void wcombine_kernel() {
    int idx = blockIdx.x * blockDim.x + threadIdx.x;
    if (idx >= 2 * HD * HD) return;
    int l = idx / (HD * HD), r = idx % (HD * HD);
    int n = r >> 7, k = r & 127;
    int e = k * HD + n;
    int base = l * 3 * HD * HD;
    int o = l * HD * HD + n * HD + k;
    g_WXgT[o] = __float2half(0.5f * (g_W1f[base + e] + g_W1f[base + 2 * HD * HD + e]));
    g_WAgT[o] = __float2half(0.5f * g_W2f[base + e]);
    g_WRgT[o] = __float2half(0.5f * g_W2f[base + 2 * HD * HD + e]);
    g_WXdT[o] = __float2half(g_W1f[base + HD * HD + e]);
    g_WAdT[o] = __float2half(g_W2f[base + HD * HD + e]);
    if (r < HD) {
        g_Bg[l * HD + r] = 0.5f * (g_bf[l * 3 * HD + r] + g_bf[(l * 3 + 2) * HD + r]);
        g_Bd[l * HD + r] = g_bf[(l * 3 + 1) * HD + r];
    }
}

// ---------------- BN finalize -------------------------------------------------------
__global__ void bnfinal_kernel(const float* __restrict__ gamma, const float* __restrict__ beta) {
    int t = threadIdx.x;
    float inv_n = (t < HD) ? (1.0f / NGn) : (1.0f / NDn);
    float m = g_sum[t] * inv_n;
    float v = g_ssq[t] * inv_n - m * m;
    float a = rsqrtf(v + 1e-5f) * gamma[t];
    g_bnA[t] = a;
    g_bnB[t] = beta[t] - m * a;
}

// ---------------- mean aggregation (fp16 gather; 8B per lane per edge) --------------
__device__ __forceinline__ void acc_h4(float4& a, uint2 u) {
    float2 f0 = __half22float2(*(__half2*)&u.x);
    float2 f1 = __half22float2(*(__half2*)&u.y);
    a.x += f0.x; a.y += f0.y; a.z += f1.x; a.w += f1.y;
}
__device__ __forceinline__ void acc_h4_bn(float4& a, uint2 u, float4 av, float4 bv) {
    float2 f0 = __half22float2(*(__half2*)&u.x);
    float2 f1 = __half22float2(*(__half2*)&u.y);
    float x0 = fmaf(av.x, f0.x, bv.x); x0 = (x0 >= 0.f) ? x0 : 0.01f * x0;
    float x1 = fmaf(av.y, f0.y, bv.y); x1 = (x1 >= 0.f) ? x1 : 0.01f * x1;
    float x2 = fmaf(av.z, f1.x, bv.z); x2 = (x2 >= 0.f) ? x2 : 0.01f * x2;
    float x3 = fmaf(av.w, f1.y, bv.w); x3 = (x3 >= 0.f) ? x3 : 0.01f * x3;
    a.x += x0; a.y += x1; a.z += x2; a.w += x3;
}

__global__ void agg_all_kernel(int l) {
    int w = (blockIdx.x * blockDim.x + threadIdx.x) >> 5;
    int lane = threadIdx.x & 31;
    int etype, dst;
    if (w < NGn)                { etype = 0; dst = w; }
    else if (w < 2 * NGn)       { etype = 1; dst = w - NGn; }
    else if (w < 2 * NGn + NDn) { etype = 2; dst = w - 2 * NGn; }
    else return;

    const __half* __restrict__ xsrc;
    float* agg;
    const int* __restrict__ csr;
    int soff;
    if (etype == 0)      { xsrc = l ? g_hg1 : g_hxg; agg = g_aggA; csr = g_csr_gg;  soff = 0; }
    else if (etype == 1) { xsrc = l ? g_hd1 : g_hxd; agg = g_aggB; csr = g_csr_rev; soff = HD; }
    else                 { xsrc = l ? g_hg1 : g_hxg; agg = g_aggD; csr = g_csr_gda; soff = 0; }

    int o = off_of(etype)[dst];
    int c = cnt_of(etype)[dst];
    const int* __restrict__ p = csr + o;
    int coff = lane * 4;

    float4 av = make_float4(1.f, 1.f, 1.f, 1.f), bv = make_float4(0.f, 0.f, 0.f, 0.f);
    if (l) {
        av = *(const float4*)&g_bnA[soff + coff];
        bv = *(const float4*)&g_bnB[soff + coff];
    }

    float4 a0 = make_float4(0.f,0.f,0.f,0.f), a1 = a0, a2 = a0, a3 = a0;
    int j = 0;
    if (l) {
        for (; j + 4 <= c; j += 4) {
            uint2 u0 = *(const uint2*)(xsrc + (size_t)p[j]     * HD + coff);
            uint2 u1 = *(const uint2*)(xsrc + (size_t)p[j + 1] * HD + coff);
            uint2 u2 = *(const uint2*)(xsrc + (size_t)p[j + 2] * HD + coff);
            uint2 u3 = *(const uint2*)(xsrc + (size_t)p[j + 3] * HD + coff);
            acc_h4_bn(a0, u0, av, bv);
            acc_h4_bn(a1, u1, av, bv);
            acc_h4_bn(a2, u2, av, bv);
            acc_h4_bn(a3, u3, av, bv);
        }
        for (; j < c; j++) {
            uint2 u = *(const uint2*)(xsrc + (size_t)p[j] * HD + coff);
            acc_h4_bn(a0, u, av, bv);
        }
    } else {
        for (; j + 4 <= c; j += 4) {
            uint2 u0 = *(const uint2*)(xsrc + (size_t)p[j]     * HD + coff);
            uint2 u1 = *(const uint2*)(xsrc + (size_t)p[j + 1] * HD + coff);
            uint2 u2 = *(const uint2*)(xsrc + (size_t)p[j + 2] * HD + coff);
            uint2 u3 = *(const uint2*)(xsrc + (size_t)p[j + 3] * HD + coff);
            acc_h4(a0, u0);
            acc_h4(a1, u1);
            acc_h4(a2, u2);
            acc_h4(a3, u3);
        }
        for (; j < c; j++) {
            uint2 u = *(const uint2*)(xsrc + (size_t)p[j] * HD + coff);
            acc_h4(a0, u);
        }
    }
    a0.x += a1.x + a2.x + a3.x;
    a0.y += a1.y + a2.y + a3.y;
    a0.z += a1.z + a2.z + a3.z;
    a0.w += a1.w + a2.w + a3.w;
    float sc = 1.0f / fmaxf((float)c, 1.0f);
    a0.x *= sc; a0.y *= sc; a0.z *= sc; a0.w *= sc;
    *(float4*)(agg + (size_t)dst * HD + coff) = a0;
}

// ---------------- fp16 mma GEMM, cp.async double-buffered (R12-proven) --------------
#define PITCH 36
#define XBUF_WORDS (128 * PITCH)
#define WBUF_HALVES (128 * 40)
#define SA_WORD_OFF (2 * XBUF_WORDS + WBUF_HALVES)
#define GEMM_SMEM ((SA_WORD_OFF + 256) * 4)

__global__ __launch_bounds__(256) void gemm_async_kernel(const float* __restrict__ x_gene,
                                                         const float* __restrict__ x_dis,
                                                         int l, int nblkG) {
    extern __shared__ uint32_t smem[];
    uint32_t sbase = smem_u32(smem);
    uint32_t xs_base = sbase;
    uint32_t ws_base = sbase + 2 * XBUF_WORDS * 4;
    float (*Xsf)[128][PITCH] = (float(*)[128][PITCH])smem;
    __half* wsH = (__half*)(smem + 2 * XBUF_WORDS);
    float* sA = (float*)(smem + SA_WORD_OFF);
    float* sB = sA + 128;

    bool isG = blockIdx.x < (unsigned)nblkG;
    int nsrc = isG ? 3 : 2;
    int row0 = (isG ? blockIdx.x : (blockIdx.x - nblkG)) * 128;
    int nrows = isG ? NGn : NDn;
    int soff = isG ? 0 : HD;

    const float *X0, *X1, *X2 = nullptr;
    const __half *W0, *W1, *W2 = nullptr;
    const float* bias;
    float* out;
    __half* hmir = nullptr;
    if (isG) {
        X0 = l ? g_g1 : x_gene; X1 = g_aggA; X2 = g_aggB;
        W0 = g_WXgT + l * HD * HD; W1 = g_WAgT + l * HD * HD; W2 = g_WRgT + l * HD * HD;
        bias = g_Bg + l * HD; out = l ? g_g2 : g_g1;
        if (!l) hmir = g_hg1;
    } else {
        X0 = l ? g_d1 : x_dis; X1 = g_aggD;
        W0 = g_WXdT + l * HD * HD; W1 = g_WAdT + l * HD * HD;
        bias = g_Bd + l * HD; out = l ? g_d2 : g_d1;
        if (!l) hmir = g_hd1;
    }

    int tid = threadIdx.x;
    int warp = tid >> 5, lane = tid & 31;
    int g = lane >> 2, tg = lane & 3;
    int rw = warp >> 1, cw = warp & 1;

    if (l && tid < 128) {
        sA[tid] = g_bnA[soff + tid];
        sB[tid] = g_bnB[soff + tid];
    }

    int xr = tid >> 3;
    int xq = (tid & 7) * 4;
    int wn = tid & 127;
    int wq = tid >> 7;

    int nch = nsrc * 4;

    auto stage = [&](int c, int buf) {
        int s = c >> 2, k0 = (c & 3) * 32;
        const float* Xp = (s == 0) ? X0 : ((s == 1) ? X1 : X2);
        const __half* Wp = (s == 0) ? W0 : ((s == 1) ? W1 : W2);
        #pragma unroll
        for (int i = 0; i < 4; i++) {
            int r = xr + i * 32;
            const float* src = Xp + (size_t)(row0 + r) * HD + k0 + xq;
            uint32_t dst = xs_base + (uint32_t)(buf * XBUF_WORDS + r * PITCH + xq) * 4;
            cp_async16(dst, src, (row0 + r < nrows) ? 16 : 0);
        }
        #pragma unroll
        for (int i = 0; i < 2; i++) {
            int q = wq + i * 2;
            const __half* src = Wp + (size_t)wn * HD + k0 + q * 8;
            uint32_t dst = ws_base + (uint32_t)(buf * WBUF_HALVES + wn * 40 + q * 8) * 2;
            cp_async16(dst, src, 16);
        }
        cp_commit();
    };

    float acc[2][8][4];
    #pragma unroll
    for (int mt = 0; mt < 2; mt++)
        #pragma unroll
        for (int nt = 0; nt < 8; nt++)
            #pragma unroll
            for (int i = 0; i < 4; i++) acc[mt][nt][i] = 0.f;

    stage(0, 0);
    stage(1, 1);

    for (int c = 0; c < nch; c++) {
        int buf = c & 1;
        if (c + 1 < nch) cp_wait1(); else cp_wait0();
        __syncthreads();

        bool bn = (l != 0) && (c < 4);
        int k0c = (c & 3) * 32;

        #pragma unroll
        for (int k16 = 0; k16 < 2; k16++) {
            int kb = k16 * 16;
            uint32_t b[8][2];
            #pragma unroll
            for (int nt = 0; nt < 8; nt++) {
                const __half* wr = wsH + buf * WBUF_HALVES + (cw * 64 + nt * 8 + g) * 40 + kb + 2 * tg;
                b[nt][0] = *(const uint32_t*)wr;
                b[nt][1] = *(const uint32_t*)(wr + 8);
            }
            float2 aaL, bbL, aaH, bbH;
            if (bn) {
                int c0 = k0c + kb + 2 * tg;
                aaL = *(const float2*)&sA[c0];     bbL = *(const float2*)&sB[c0];
                aaH = *(const float2*)&sA[c0 + 8]; bbH = *(const float2*)&sB[c0 + 8];
            }
            uint32_t a[2][4];
            #pragma unroll
            for (int mt = 0; mt < 2; mt++) {
                int rb = rw * 32 + mt * 16;
                float2 x0 = *(const float2*)&Xsf[buf][rb + g][kb + 2 * tg];
                float2 x1 = *(const float2*)&Xsf[buf][rb + g + 8][kb + 2 * tg];
                float2 x2 = *(const float2*)&Xsf[buf][rb + g][kb + 2 * tg + 8];
                float2 x3 = *(const float2*)&Xsf[buf][rb + g + 8][kb + 2 * tg + 8];
                if (bn) {
                    x0.x = fmaf(aaL.x, x0.x, bbL.x); x0.x = (x0.x >= 0.f) ? x0.x : 0.01f * x0.x;
                    x0.y = fmaf(aaL.y, x0.y, bbL.y); x0.y = (x0.y >= 0.f) ? x0.y : 0.01f * x0.y;
                    x1.x = fmaf(aaL.x, x1.x, bbL.x); x1.x = (x1.x >= 0.f) ? x1.x : 0.01f * x1.x;
                    x1.y = fmaf(aaL.y, x1.y, bbL.y); x1.y = (x1.y >= 0.f) ? x1.y : 0.01f * x1.y;
                    x2.x = fmaf(aaH.x, x2.x, bbH.x); x2.x = (x2.x >= 0.f) ? x2.x : 0.01f * x2.x;
                    x2.y = fmaf(aaH.y, x2.y, bbH.y); x2.y = (x2.y >= 0.f) ? x2.y : 0.01f * x2.y;
                    x3.x = fmaf(aaH.x, x3.x, bbH.x); x3.x = (x3.x >= 0.f) ? x3.x : 0.01f * x3.x;
                    x3.y = fmaf(aaH.y, x3.y, bbH.y); x3.y = (x3.y >= 0.f) ? x3.y : 0.01f * x3.y;
                }
                a[mt][0] = packh2(x0.x, x0.y);
                a[mt][1] = packh2(x1.x, x1.y);
                a[mt][2] = packh2(x2.x, x2.y);
                a[mt][3] = packh2(x3.x, x3.y);
            }
            #pragma unroll
            for (int mt = 0; mt < 2; mt++)
                #pragma unroll
                for (int nt = 0; nt < 8; nt++)
                    mma_f16(acc[mt][nt], a[mt], b[nt]);
        }
        __syncthreads();
        if (c + 2 < nch) stage(c + 2, buf);
    }

    // epilogue: bias add, store, fp16 mirror, layer-1 BN column stats
    bool do_stats = (l == 0);
    #pragma unroll
    for (int nt = 0; nt < 8; nt++) {
        int col = cw * 64 + nt * 8 + 2 * tg;
        float2 bv = *(const float2*)(bias + col);
        float s0 = 0.f, s1 = 0.f, q0 = 0.f, q1 = 0.f;
        #pragma unroll
        for (int mt = 0; mt < 2; mt++) {
            int r0 = row0 + rw * 32 + mt * 16 + g;
            if (r0 < nrows) {
                float y0 = acc[mt][nt][0] + bv.x;
                float y1 = acc[mt][nt][1] + bv.y;
                *(float2*)(out + (size_t)r0 * HD + col) = make_float2(y0, y1);
                if (hmir) *(uint32_t*)(hmir + (size_t)r0 * HD + col) = packh2(y0, y1);
                s0 += y0; s1 += y1; q0 += y0 * y0; q1 += y1 * y1;
            }
            int r1 = r0 + 8;
            if (r1 < nrows) {
                float y0 = acc[mt][nt][2] + bv.x;
                float y1 = acc[mt][nt][3] + bv.y;
                *(float2*)(out + (size_t)r1 * HD + col) = make_float2(y0, y1);
                if (hmir) *(uint32_t*)(hmir + (size_t)r1 * HD + col) = packh2(y0, y1);
                s0 += y0; s1 += y1; q0 += y0 * y0; q1 += y1 * y1;
            }
        }
        if (do_stats) {
            #pragma unroll
            for (int m = 4; m <= 16; m <<= 1) {
                s0 += __shfl_xor_sync(0xffffffffu, s0, m);
                s1 += __shfl_xor_sync(0xffffffffu, s1, m);
                q0 += __shfl_xor_sync(0xffffffffu, q0, m);
                q1 += __shfl_xor_sync(0xffffffffu, q1, m);
            }
            if (g == 0) {
                atomicAdd(&g_sum[soff + col], s0);
                atomicAdd(&g_sum[soff + col + 1], s1);
                atomicAdd(&g_ssq[soff + col], q0);
                atomicAdd(&g_ssq[soff + col + 1], q1);
            }
        }
    }
}

// ---------------- decoder (fp32) ----------------------------------------------------
__global__ void decoder_kernel(const int* __restrict__ ls, const int* __restrict__ ld,
                               float* __restrict__ out, int n) {
    int e = (blockIdx.x * blockDim.x + threadIdx.x) >> 5;
    int lane = threadIdx.x & 31;
    if (e >= n) return;
    int a = ls[e], b = ld[e];
    float4 u = *(const float4*)(g_g2 + (size_t)a * HD + lane * 4);
    float4 v = *(const float4*)(g_d2 + (size_t)b * HD + lane * 4);
    float p = u.x * v.x + u.y * v.y + u.z * v.z + u.w * v.w;
    #pragma unroll
    for (int off = 16; off > 0; off >>= 1)
        p += __shfl_xor_sync(0xffffffffu, p, off);
    if (lane == 0) out[e] = p;
}

// ---------------- launch ------------------------------------------------------------
extern "C" void kernel_launch(void* const* d_in, const int* in_sizes, int n_in,
                              void* d_out, int out_size) {
    const float* x_gene  = (const float*)d_in[0];
    const float* x_dis   = (const float*)d_in[1];
    const float* W_dst1  = (const float*)d_in[2];
    const float* W_src1  = (const float*)d_in[3];
    const float* W_upd1  = (const float*)d_in[4];
    const float* b_dst1  = (const float*)d_in[5];
    const float* b_src1  = (const float*)d_in[6];
    const float* b_upd1  = (const float*)d_in[7];
    const float* W_dst2  = (const float*)d_in[8];
    const float* W_src2  = (const float*)d_in[9];
    const float* W_upd2  = (const float*)d_in[10];
    const float* b_dst2  = (const float*)d_in[11];
    const float* b_src2  = (const float*)d_in[12];
    const float* b_upd2  = (const float*)d_in[13];
    const float* bn_gamma = (const float*)d_in[14];
    const float* bn_beta  = (const float*)d_in[15];
    const int* gg_src  = (const int*)d_in[16];
    const int* gg_dst  = (const int*)d_in[17];
    const int* gda_src = (const int*)d_in[18];
    const int* gda_dst = (const int*)d_in[19];
    const int* label_src = (const int*)d_in[20];
    const int* label_dst = (const int*)d_in[21];
    float* out = (float*)d_out;

    cudaFuncSetAttribute(gemm_async_kernel, cudaFuncAttributeMaxDynamicSharedMemorySize, GEMM_SMEM);

    // side stream + events for fork-join capture (created once, outside capture)
    static cudaStream_t s1 = nullptr;
    static cudaEvent_t evFork = nullptr, evJoin = nullptr;
    if (!s1) {
        cudaStreamCreate(&s1);
        cudaEventCreateWithFlags(&evFork, cudaEventDisableTiming);
        cudaEventCreateWithFlags(&evJoin, cudaEventDisableTiming);
    }

    void *p_cnt_gg, *p_cnt_rev, *p_cnt_gda, *p_sum, *p_ssq;
    cudaGetSymbolAddress(&p_cnt_gg, g_cnt_gg);
    cudaGetSymbolAddress(&p_cnt_rev, g_cnt_rev);
    cudaGetSymbolAddress(&p_cnt_gda, g_cnt_gda);
    cudaGetSymbolAddress(&p_sum, g_sum);
    cudaGetSymbolAddress(&p_ssq, g_ssq);

    // fork: side chain (tohalf -> wprep -> wcombine) runs concurrent with CSR chain
    cudaEventRecord(evFork, 0);
    cudaStreamWaitEvent(s1, evFork, 0);
    tohalf_kernel<<<2048, 256, 0, s1>>>(x_gene, x_dis);
    wprep_kernel<<<54, 256, 0, s1>>>(W_dst1, W_src1, W_upd1, W_dst2, W_src2, W_upd2,
                                     b_dst1, b_src1, b_upd1, b_dst2, b_src2, b_upd2);
    wcombine_kernel<<<(2 * HD * HD + 255) / 256, 256, 0, s1>>>();
    cudaEventRecord(evJoin, s1);

    // main chain: zeroing + CSR build
    cudaMemsetAsync(p_cnt_gg, 0, NGn * sizeof(int));
    cudaMemsetAsync(p_cnt_rev, 0, NGn * sizeof(int));
    cudaMemsetAsync(p_cnt_gda, 0, NDn * sizeof(int));
    cudaMemsetAsync(p_sum, 0, 2 * HD * sizeof(float));
    cudaMemsetAsync(p_ssq, 0, 2 * HD * sizeof(float));
    hist_all_kernel<<<4096, 256>>>(gg_dst, gda_src, gda_dst);
    scan_phase1<<<NBTOT, 256>>>();
    scan_phase3<<<NBTOT, 256>>>();
    fill_all_kernel<<<4096, 256>>>(gg_src, gg_dst, gda_src, gda_dst);

    // join before the layer loop (agg needs tohalf + CSR; gemm needs weights)
    cudaStreamWaitEvent(0, evJoin, 0);

    const int aggWarps = 2 * NGn + NDn;
    const int aggBlk = (aggWarps * 32 + 255) / 256;
    const int nblkG = (NGn + 127) / 128;
    const int nblkD = (NDn + 127) / 128;

    for (int l = 0; l < 2; l++) {
        agg_all_kernel<<<aggBlk, 256>>>(l);
        gemm_async_kernel<<<nblkG + nblkD, 256, GEMM_SMEM>>>(x_gene, x_dis, l, nblkG);
        if (l == 0)
            bnfinal_kernel<<<1, 256>>>(bn_gamma, bn_beta);
    }

    decoder_kernel<<<(ELABn * 32 + 255) / 256, 256>>>(label_src, label_dst, out, ELABn);
}

// round 16
// speedup vs baseline: 1.0859x; 1.0038x over previous
#include <cuda_runtime.h>
#include <cuda_fp16.h>
#include <math.h>
#include <stdint.h>

#define NGn   50000
#define NDn   20000
#define HD    128
#define EGGn  800000
#define EGDAn 400000
#define ELABn 200000

// ---------------- scratch (static device allocations; no cudaMalloc) ----------------
__device__ float g_aggA[(size_t)NGn * HD];
__device__ float g_aggB[(size_t)NGn * HD];
__device__ float g_aggD[(size_t)NDn * HD];
__device__ float g_g1[(size_t)NGn * HD];
__device__ float g_d1[(size_t)NDn * HD];
__device__ float g_g2[(size_t)NGn * HD];
__device__ float g_d2[(size_t)NDn * HD];
// fp16 gather mirrors
__device__ __half g_hxg[(size_t)NGn * HD];
__device__ __half g_hxd[(size_t)NDn * HD];
__device__ __half g_hg1[(size_t)NGn * HD];
__device__ __half g_hd1[(size_t)NDn * HD];

__device__ float g_W1f[2 * 3 * HD * HD];
__device__ float g_W2f[2 * 3 * HD * HD];
__device__ float g_bf [2 * 3 * HD];
__device__ __half g_WXgT[2 * HD * HD], g_WAgT[2 * HD * HD], g_WRgT[2 * HD * HD];
__device__ __half g_WXdT[2 * HD * HD], g_WAdT[2 * HD * HD];
__device__ float g_Bg[2 * HD], g_Bd[2 * HD];

__device__ int g_cnt_gg[NGn], g_cnt_rev[NGn], g_cnt_gda[NDn];
__device__ int g_off_gg[NGn], g_off_rev[NGn], g_off_gda[NDn];
__device__ int g_cur_gg[NGn], g_cur_rev[NGn], g_cur_gda[NDn];
__device__ int g_csr_gg[EGGn], g_csr_rev[EGDAn], g_csr_gda[EGDAn];
__device__ int g_bsum[160];
__device__ float g_sum[2 * HD], g_ssq[2 * HD];
__device__ float g_bnA[2 * HD], g_bnB[2 * HD];

#define NBG 49
#define NBD 20
#define NBTOT (NBG + NBG + NBD)

// ---------------- selectors ---------------------------------------------------------
__device__ __forceinline__ int* cnt_of(int e) { return e == 0 ? g_cnt_gg : (e == 1 ? g_cnt_rev : g_cnt_gda); }
__device__ __forceinline__ int* off_of(int e) { return e == 0 ? g_off_gg : (e == 1 ? g_off_rev : g_off_gda); }
__device__ __forceinline__ int  ndst_of(int e){ return e == 2 ? NDn : NGn; }

// ---------------- small PTX helpers --------------------------------------------------
__device__ __forceinline__ uint32_t smem_u32(const void* p) {
    uint32_t a;
    asm("{ .reg .u64 t; cvta.to.shared.u64 t, %1; cvt.u32.u64 %0, t; }" : "=r"(a) : "l"(p));
    return a;
}
__device__ __forceinline__ void cp_async16(uint32_t dst, const void* src, int src_bytes) {
    asm volatile("cp.async.ca.shared.global [%0], [%1], 16, %2;"
                 :: "r"(dst), "l"(src), "r"(src_bytes) : "memory");
}
__device__ __forceinline__ void cp_commit() { asm volatile("cp.async.commit_group;" ::: "memory"); }
__device__ __forceinline__ void cp_wait1() { asm volatile("cp.async.wait_group 1;" ::: "memory"); }
__device__ __forceinline__ void cp_wait0() { asm volatile("cp.async.wait_group 0;" ::: "memory"); }

__device__ __forceinline__ void mma_f16(float* d, const uint32_t* a, const uint32_t* b) {
    asm volatile(
        "mma.sync.aligned.m16n8k16.row.col.f32.f16.f16.f32 "
        "{%0,%1,%2,%3}, {%4,%5,%6,%7}, {%8,%9}, {%0,%1,%2,%3};\n"
        : "+f"(d[0]), "+f"(d[1]), "+f"(d[2]), "+f"(d[3])
        : "r"(a[0]), "r"(a[1]), "r"(a[2]), "r"(a[3]), "r"(b[0]), "r"(b[1]));
}
__device__ __forceinline__ uint32_t packh2(float lo, float hi) {
    __half2 h = __floats2half2_rn(lo, hi);
    return *(uint32_t*)&h;
}

// ---------------- CSR build ---------------------------------------------------------
__global__ void hist_all_kernel(const int* __restrict__ gg_dst,
                                const int* __restrict__ gda_src,
                                const int* __restrict__ gda_dst) {
    int total = EGGn + 2 * EGDAn;
    for (int i = blockIdx.x * blockDim.x + threadIdx.x; i < total; i += gridDim.x * blockDim.x) {
        if (i < EGGn) atomicAdd(&g_cnt_gg[gg_dst[i]], 1);
        else if (i < EGGn + EGDAn) atomicAdd(&g_cnt_rev[gda_src[i - EGGn]], 1);
        else atomicAdd(&g_cnt_gda[gda_dst[i - EGGn - EGDAn]], 1);
    }
}

__device__ __forceinline__ void scan_map(int b, int& e, int& chunk) {
    if (b < NBG)          { e = 0; chunk = b; }
    else if (b < 2 * NBG) { e = 1; chunk = b - NBG; }
    else                  { e = 2; chunk = b - 2 * NBG; }
}

__global__ void scan_phase1() {
    int e, chunk; scan_map(blockIdx.x, e, chunk);
    const int* cnt = cnt_of(e);
    int n = ndst_of(e);
    int base = chunk * 1024;
    int s = 0;
    for (int i = threadIdx.x; i < 1024; i += 256) {
        int idx = base + i;
        if (idx < n) s += cnt[idx];
    }
    __shared__ int red[256];
    red[threadIdx.x] = s; __syncthreads();
    for (int d = 128; d > 0; d >>= 1) {
        if (threadIdx.x < d) red[threadIdx.x] += red[threadIdx.x + d];
        __syncthreads();
    }
    if (threadIdx.x == 0) g_bsum[blockIdx.x] = red[0];
}

// phase3 with built-in segment prefix (g_bsum holds RAW per-chunk sums)
__global__ void scan_phase3() {
    int e, chunk; scan_map(blockIdx.x, e, chunk);
    const int* cnt = cnt_of(e);
    int* off = off_of(e);
    int* cur = (e == 0) ? g_cur_gg : (e == 1 ? g_cur_rev : g_cur_gda);
    int n = ndst_of(e);
    int segbase = (e == 0) ? 0 : (e == 1 ? NBG : 2 * NBG);

    __shared__ int sPrefix;
    if (threadIdx.x < 32) {
        int lane = threadIdx.x;
        int s = 0;
        if (lane < chunk) s += g_bsum[segbase + lane];
        if (lane + 32 < chunk) s += g_bsum[segbase + lane + 32];
        #pragma unroll
        for (int d = 16; d > 0; d >>= 1)
            s += __shfl_xor_sync(0xffffffffu, s, d);
        if (lane == 0) sPrefix = s;
    }

    int base = chunk * 1024;
    int v[4]; int lsum = 0;
    int i0 = base + threadIdx.x * 4;
    #pragma unroll
    for (int j = 0; j < 4; j++) { v[j] = (i0 + j < n) ? cnt[i0 + j] : 0; lsum += v[j]; }
    __shared__ int ps[256];
    ps[threadIdx.x] = lsum; __syncthreads();
    for (int d = 1; d < 256; d <<= 1) {
        int t = (threadIdx.x >= d) ? ps[threadIdx.x - d] : 0;
        __syncthreads();
        ps[threadIdx.x] += t;
        __syncthreads();
    }
    int run = sPrefix + ps[threadIdx.x] - lsum;
    #pragma unroll
    for (int j = 0; j < 4; j++) {
        if (i0 + j < n) { off[i0 + j] = run; cur[i0 + j] = run; }
        run += v[j];
    }
}

__global__ void fill_all_kernel(const int* __restrict__ gg_src, const int* __restrict__ gg_dst,
                                const int* __restrict__ gda_src, const int* __restrict__ gda_dst) {
    int total = EGGn + 2 * EGDAn;
    for (int i = blockIdx.x * blockDim.x + threadIdx.x; i < total; i += gridDim.x * blockDim.x) {
        if (i < EGGn) {
            int p = atomicAdd(&g_cur_gg[gg_dst[i]], 1);
            g_csr_gg[p] = gg_src[i];
        } else if (i < EGGn + EGDAn) {
            int j = i - EGGn;
            int p = atomicAdd(&g_cur_rev[gda_src[j]], 1);
            g_csr_rev[p] = gda_dst[j];
        } else {
            int j = i - EGGn - EGDAn;
            int p = atomicAdd(&g_cur_gda[gda_dst[j]], 1);
            g_csr_gda[p] = gda_src[j];
        }
    }
}

// ---------------- fp16 mirror of input features -------------------------------------
__global__ void tohalf_kernel(const float* __restrict__ xg, const float* __restrict__ xd) {
    size_t totalG = (size_t)NGn * HD / 4;
    size_t total = totalG + (size_t)NDn * HD / 4;
    for (size_t i = (size_t)blockIdx.x * blockDim.x + threadIdx.x; i < total;
         i += (size_t)gridDim.x * blockDim.x) {
        const float* src; __half* dst; size_t e;
        if (i < totalG) { src = xg; dst = g_hxg; e = i * 4; }
        else { src = xd; dst = g_hxd; e = (i - totalG) * 4; }
        float4 v = *(const float4*)(src + e);
        __half2 h0 = __floats2half2_rn(v.x, v.y);
        __half2 h1 = __floats2half2_rn(v.z, v.w);
        *(uint2*)(dst + e) = make_uint2(*(uint32_t*)&h0, *(uint32_t*)&h1);
    }
}

// ---------------- fused weight precompute -------------------------------------------
__global__ void wprep_kernel(const float* __restrict__ Wd1, const float* __restrict__ Ws1,
                             const float* __restrict__ Wu1, const float* __restrict__ Wd2,
                             const float* __restrict__ Ws2, const float* __restrict__ Wu2,
                             const float* __restrict__ bd1, const float* __restrict__ bs1,
                             const float* __restrict__ bu1, const float* __restrict__ bd2,
                             const float* __restrict__ bs2, const float* __restrict__ bu2) {
    int b = blockIdx.x;
    if (b < 48) {
        int l = b / 24, i = (b / 8) % 3, rc = b % 8;
        const float* Wd = (l ? Wd2 : Wd1) + i * HD * HD;
        const float* Ws = (l ? Ws2 : Ws1) + i * HD * HD;
        const float* Wu = (l ? Wu2 : Wu1) + i * 2 * HD * HD;
        int h  = threadIdx.x & 127;
        int dg = threadIdx.x >> 7;
        int d0 = rc * 16 + dg * 8;
        float a1[8], a2[8];
        #pragma unroll
        for (int r = 0; r < 8; r++) { a1[r] = 0.f; a2[r] = 0.f; }
        for (int k = 0; k < HD; k++) {
            float wt = Wu[k * HD + h];
            float wb = Wu[(k + HD) * HD + h];
            #pragma unroll
            for (int r = 0; r < 8; r++) {
                a1[r] += Wd[(d0 + r) * HD + k] * wt;
                a2[r] += Ws[(d0 + r) * HD + k] * wb;
            }
        }
        int base = (l * 3 + i) * HD * HD;
        #pragma unroll
        for (int r = 0; r < 8; r++) {
            g_W1f[base + (d0 + r) * HD + h] = a1[r];
            g_W2f[base + (d0 + r) * HD + h] = a2[r];
        }
    } else {
        int bb = b - 48;
        int l = bb / 3, i = bb % 3;
        if (threadIdx.x >= HD) return;
        const float* bd = (l ? bd2 : bd1) + i * HD;
        const float* bs = (l ? bs2 : bs1) + i * HD;
        const float* bu = (l ? bu2 : bu1) + i * HD;
        const float* Wu = (l ? Wu2 : Wu1) + i * 2 * HD * HD;
        int h = threadIdx.x;
        float acc = bu[h];
        for (int k = 0; k < HD; k++)
            acc += bd[k] * Wu[k * HD + h] + bs[k] * Wu[(k + HD) * HD + h];
        g_bf[(l * 3 + i) * HD + h] = acc;
    }
}

__global__ void wcombine_kernel() {
    int idx = blockIdx.x * blockDim.x + threadIdx.x;
    if (idx >= 2 * HD * HD) return;
    int l = idx / (HD * HD), r = idx % (HD * HD);
    int n = r >> 7, k = r & 127;
    int e = k * HD + n;
    int base = l * 3 * HD * HD;
    int o = l * HD * HD + n * HD + k;
    g_WXgT[o] = __float2half(0.5f * (g_W1f[base + e] + g_W1f[base + 2 * HD * HD + e]));
    g_WAgT[o] = __float2half(0.5f * g_W2f[base + e]);
    g_WRgT[o] = __float2half(0.5f * g_W2f[base + 2 * HD * HD + e]);
    g_WXdT[o] = __float2half(g_W1f[base + HD * HD + e]);
    g_WAdT[o] = __float2half(g_W2f[base + HD * HD + e]);
    if (r < HD) {
        g_Bg[l * HD + r] = 0.5f * (g_bf[l * 3 * HD + r] + g_bf[(l * 3 + 2) * HD + r]);
        g_Bd[l * HD + r] = g_bf[(l * 3 + 1) * HD + r];
    }
}

// ---------------- BN finalize -------------------------------------------------------
__global__ void bnfinal_kernel(const float* __restrict__ gamma, const float* __restrict__ beta) {
    int t = threadIdx.x;
    float inv_n = (t < HD) ? (1.0f / NGn) : (1.0f / NDn);
    float m = g_sum[t] * inv_n;
    float v = g_ssq[t] * inv_n - m * m;
    float a = rsqrtf(v + 1e-5f) * gamma[t];
    g_bnA[t] = a;
    g_bnB[t] = beta[t] - m * a;
}

// ---------------- mean aggregation (fp16 gather; warp-range parameterized) ----------
__device__ __forceinline__ void acc_h4(float4& a, uint2 u) {
    float2 f0 = __half22float2(*(__half2*)&u.x);
    float2 f1 = __half22float2(*(__half2*)&u.y);
    a.x += f0.x; a.y += f0.y; a.z += f1.x; a.w += f1.y;
}
__device__ __forceinline__ void acc_h4_bn(float4& a, uint2 u, float4 av, float4 bv) {
    float2 f0 = __half22float2(*(__half2*)&u.x);
    float2 f1 = __half22float2(*(__half2*)&u.y);
    float x0 = fmaf(av.x, f0.x, bv.x); x0 = (x0 >= 0.f) ? x0 : 0.01f * x0;
    float x1 = fmaf(av.y, f0.y, bv.y); x1 = (x1 >= 0.f) ? x1 : 0.01f * x1;
    float x2 = fmaf(av.z, f1.x, bv.z); x2 = (x2 >= 0.f) ? x2 : 0.01f * x2;
    float x3 = fmaf(av.w, f1.y, bv.w); x3 = (x3 >= 0.f) ? x3 : 0.01f * x3;
    a.x += x0; a.y += x1; a.z += x2; a.w += x3;
}

// wbase: starting warp index. gene chain: wbase=0, covers [0, 2*NGn); disease: wbase=2*NGn.
__global__ void agg_all_kernel(int l, int wbase, int wcount) {
    int wi = (blockIdx.x * blockDim.x + threadIdx.x) >> 5;
    if (wi >= wcount) return;
    int w = wbase + wi;
    int lane = threadIdx.x & 31;
    int etype, dst;
    if (w < NGn)                { etype = 0; dst = w; }
    else if (w < 2 * NGn)       { etype = 1; dst = w - NGn; }
    else                        { etype = 2; dst = w - 2 * NGn; }

    const __half* __restrict__ xsrc;
    float* agg;
    const int* __restrict__ csr;
    int soff;
    if (etype == 0)      { xsrc = l ? g_hg1 : g_hxg; agg = g_aggA; csr = g_csr_gg;  soff = 0; }
    else if (etype == 1) { xsrc = l ? g_hd1 : g_hxd; agg = g_aggB; csr = g_csr_rev; soff = HD; }
    else                 { xsrc = l ? g_hg1 : g_hxg; agg = g_aggD; csr = g_csr_gda; soff = 0; }

    int o = off_of(etype)[dst];
    int c = cnt_of(etype)[dst];
    const int* __restrict__ p = csr + o;
    int coff = lane * 4;

    float4 av = make_float4(1.f, 1.f, 1.f, 1.f), bv = make_float4(0.f, 0.f, 0.f, 0.f);
    if (l) {
        av = *(const float4*)&g_bnA[soff + coff];
        bv = *(const float4*)&g_bnB[soff + coff];
    }

    float4 a0 = make_float4(0.f,0.f,0.f,0.f), a1 = a0, a2 = a0, a3 = a0;
    int j = 0;
    if (l) {
        for (; j + 4 <= c; j += 4) {
            uint2 u0 = *(const uint2*)(xsrc + (size_t)p[j]     * HD + coff);
            uint2 u1 = *(const uint2*)(xsrc + (size_t)p[j + 1] * HD + coff);
            uint2 u2 = *(const uint2*)(xsrc + (size_t)p[j + 2] * HD + coff);
            uint2 u3 = *(const uint2*)(xsrc + (size_t)p[j + 3] * HD + coff);
            acc_h4_bn(a0, u0, av, bv);
            acc_h4_bn(a1, u1, av, bv);
            acc_h4_bn(a2, u2, av, bv);
            acc_h4_bn(a3, u3, av, bv);
        }
        for (; j < c; j++) {
            uint2 u = *(const uint2*)(xsrc + (size_t)p[j] * HD + coff);
            acc_h4_bn(a0, u, av, bv);
        }
    } else {
        for (; j + 4 <= c; j += 4) {
            uint2 u0 = *(const uint2*)(xsrc + (size_t)p[j]     * HD + coff);
            uint2 u1 = *(const uint2*)(xsrc + (size_t)p[j + 1] * HD + coff);
            uint2 u2 = *(const uint2*)(xsrc + (size_t)p[j + 2] * HD + coff);
            uint2 u3 = *(const uint2*)(xsrc + (size_t)p[j + 3] * HD + coff);
            acc_h4(a0, u0);
            acc_h4(a1, u1);
            acc_h4(a2, u2);
            acc_h4(a3, u3);
        }
        for (; j < c; j++) {
            uint2 u = *(const uint2*)(xsrc + (size_t)p[j] * HD + coff);
            acc_h4(a0, u);
        }
    }
    a0.x += a1.x + a2.x + a3.x;
    a0.y += a1.y + a2.y + a3.y;
    a0.z += a1.z + a2.z + a3.z;
    a0.w += a1.w + a2.w + a3.w;
    float sc = 1.0f / fmaxf((float)c, 1.0f);
    a0.x *= sc; a0.y *= sc; a0.z *= sc; a0.w *= sc;
    *(float4*)(agg + (size_t)dst * HD + coff) = a0;
}

// ---------------- fp16 mma GEMM, cp.async double-buffered (R12 body; isG param) -----
#define PITCH 36
#define XBUF_WORDS (128 * PITCH)
#define WBUF_HALVES (128 * 40)
#define SA_WORD_OFF (2 * XBUF_WORDS + WBUF_HALVES)
#define GEMM_SMEM ((SA_WORD_OFF + 256) * 4)

__global__ __launch_bounds__(256) void gemm_async_kernel(const float* __restrict__ x_gene,
                                                         const float* __restrict__ x_dis,
                                                         int l, int isGparam) {
    extern __shared__ uint32_t smem[];
    uint32_t sbase = smem_u32(smem);
    uint32_t xs_base = sbase;
    uint32_t ws_base = sbase + 2 * XBUF_WORDS * 4;
    float (*Xsf)[128][PITCH] = (float(*)[128][PITCH])smem;
    __half* wsH = (__half*)(smem + 2 * XBUF_WORDS);
    float* sA = (float*)(smem + SA_WORD_OFF);
    float* sB = sA + 128;

    bool isG = isGparam != 0;
    int nsrc = isG ? 3 : 2;
    int row0 = blockIdx.x * 128;
    int nrows = isG ? NGn : NDn;
    int soff = isG ? 0 : HD;

    const float *X0, *X1, *X2 = nullptr;
    const __half *W0, *W1, *W2 = nullptr;
    const float* bias;
    float* out;
    __half* hmir = nullptr;
    if (isG) {
        X0 = l ? g_g1 : x_gene; X1 = g_aggA; X2 = g_aggB;
        W0 = g_WXgT + l * HD * HD; W1 = g_WAgT + l * HD * HD; W2 = g_WRgT + l * HD * HD;
        bias = g_Bg + l * HD; out = l ? g_g2 : g_g1;
        if (!l) hmir = g_hg1;
    } else {
        X0 = l ? g_d1 : x_dis; X1 = g_aggD;
        W0 = g_WXdT + l * HD * HD; W1 = g_WAdT + l * HD * HD;
        bias = g_Bd + l * HD; out = l ? g_d2 : g_d1;
        if (!l) hmir = g_hd1;
    }

    int tid = threadIdx.x;
    int warp = tid >> 5, lane = tid & 31;
    int g = lane >> 2, tg = lane & 3;
    int rw = warp >> 1, cw = warp & 1;

    if (l && tid < 128) {
        sA[tid] = g_bnA[soff + tid];
        sB[tid] = g_bnB[soff + tid];
    }

    int xr = tid >> 3;
    int xq = (tid & 7) * 4;
    int wn = tid & 127;
    int wq = tid >> 7;

    int nch = nsrc * 4;

    auto stage = [&](int c, int buf) {
        int s = c >> 2, k0 = (c & 3) * 32;
        const float* Xp = (s == 0) ? X0 : ((s == 1) ? X1 : X2);
        const __half* Wp = (s == 0) ? W0 : ((s == 1) ? W1 : W2);
        #pragma unroll
        for (int i = 0; i < 4; i++) {
            int r = xr + i * 32;
            const float* src = Xp + (size_t)(row0 + r) * HD + k0 + xq;
            uint32_t dst = xs_base + (uint32_t)(buf * XBUF_WORDS + r * PITCH + xq) * 4;
            cp_async16(dst, src, (row0 + r < nrows) ? 16 : 0);
        }
        #pragma unroll
        for (int i = 0; i < 2; i++) {
            int q = wq + i * 2;
            const __half* src = Wp + (size_t)wn * HD + k0 + q * 8;
            uint32_t dst = ws_base + (uint32_t)(buf * WBUF_HALVES + wn * 40 + q * 8) * 2;
            cp_async16(dst, src, 16);
        }
        cp_commit();
    };

    float acc[2][8][4];
    #pragma unroll
    for (int mt = 0; mt < 2; mt++)
        #pragma unroll
        for (int nt = 0; nt < 8; nt++)
            #pragma unroll
            for (int i = 0; i < 4; i++) acc[mt][nt][i] = 0.f;

    stage(0, 0);
    stage(1, 1);

    for (int c = 0; c < nch; c++) {
        int buf = c & 1;
        if (c + 1 < nch) cp_wait1(); else cp_wait0();
        __syncthreads();

        bool bn = (l != 0) && (c < 4);
        int k0c = (c & 3) * 32;

        #pragma unroll
        for (int k16 = 0; k16 < 2; k16++) {
            int kb = k16 * 16;
            uint32_t b[8][2];
            #pragma unroll
            for (int nt = 0; nt < 8; nt++) {
                const __half* wr = wsH + buf * WBUF_HALVES + (cw * 64 + nt * 8 + g) * 40 + kb + 2 * tg;
                b[nt][0] = *(const uint32_t*)wr;
                b[nt][1] = *(const uint32_t*)(wr + 8);
            }
            float2 aaL, bbL, aaH, bbH;
            if (bn) {
                int c0 = k0c + kb + 2 * tg;
                aaL = *(const float2*)&sA[c0];     bbL = *(const float2*)&sB[c0];
                aaH = *(const float2*)&sA[c0 + 8]; bbH = *(const float2*)&sB[c0 + 8];
            }
            uint32_t a[2][4];
            #pragma unroll
            for (int mt = 0; mt < 2; mt++) {
                int rb = rw * 32 + mt * 16;
                float2 x0 = *(const float2*)&Xsf[buf][rb + g][kb + 2 * tg];
                float2 x1 = *(const float2*)&Xsf[buf][rb + g + 8][kb + 2 * tg];
                float2 x2 = *(const float2*)&Xsf[buf][rb + g][kb + 2 * tg + 8];
                float2 x3 = *(const float2*)&Xsf[buf][rb + g + 8][kb + 2 * tg + 8];
                if (bn) {
                    x0.x = fmaf(aaL.x, x0.x, bbL.x); x0.x = (x0.x >= 0.f) ? x0.x : 0.01f * x0.x;
                    x0.y = fmaf(aaL.y, x0.y, bbL.y); x0.y = (x0.y >= 0.f) ? x0.y : 0.01f * x0.y;
                    x1.x = fmaf(aaL.x, x1.x, bbL.x); x1.x = (x1.x >= 0.f) ? x1.x : 0.01f * x1.x;
                    x1.y = fmaf(aaL.y, x1.y, bbL.y); x1.y = (x1.y >= 0.f) ? x1.y : 0.01f * x1.y;
                    x2.x = fmaf(aaH.x, x2.x, bbH.x); x2.x = (x2.x >= 0.f) ? x2.x : 0.01f * x2.x;
                    x2.y = fmaf(aaH.y, x2.y, bbH.y); x2.y = (x2.y >= 0.f) ? x2.y : 0.01f * x2.y;
                    x3.x = fmaf(aaH.x, x3.x, bbH.x); x3.x = (x3.x >= 0.f) ? x3.x : 0.01f * x3.x;
                    x3.y = fmaf(aaH.y, x3.y, bbH.y); x3.y = (x3.y >= 0.f) ? x3.y : 0.01f * x3.y;
                }
                a[mt][0] = packh2(x0.x, x0.y);
                a[mt][1] = packh2(x1.x, x1.y);
                a[mt][2] = packh2(x2.x, x2.y);
                a[mt][3] = packh2(x3.x, x3.y);
            }
            #pragma unroll
            for (int mt = 0; mt < 2; mt++)
                #pragma unroll
                for (int nt = 0; nt < 8; nt++)
                    mma_f16(acc[mt][nt], a[mt], b[nt]);
        }
        __syncthreads();
        if (c + 2 < nch) stage(c + 2, buf);
    }

    // epilogue: bias add, store, fp16 mirror, layer-1 BN column stats
    bool do_stats = (l == 0);
    #pragma unroll
    for (int nt = 0; nt < 8; nt++) {
        int col = cw * 64 + nt * 8 + 2 * tg;
        float2 bv = *(const float2*)(bias + col);
        float s0 = 0.f, s1 = 0.f, q0 = 0.f, q1 = 0.f;
        #pragma unroll
        for (int mt = 0; mt < 2; mt++) {
            int r0 = row0 + rw * 32 + mt * 16 + g;
            if (r0 < nrows) {
                float y0 = acc[mt][nt][0] + bv.x;
                float y1 = acc[mt][nt][1] + bv.y;
                *(float2*)(out + (size_t)r0 * HD + col) = make_float2(y0, y1);
                if (hmir) *(uint32_t*)(hmir + (size_t)r0 * HD + col) = packh2(y0, y1);
                s0 += y0; s1 += y1; q0 += y0 * y0; q1 += y1 * y1;
            }
            int r1 = r0 + 8;
            if (r1 < nrows) {
                float y0 = acc[mt][nt][2] + bv.x;
                float y1 = acc[mt][nt][3] + bv.y;
                *(float2*)(out + (size_t)r1 * HD + col) = make_float2(y0, y1);
                if (hmir) *(uint32_t*)(hmir + (size_t)r1 * HD + col) = packh2(y0, y1);
                s0 += y0; s1 += y1; q0 += y0 * y0; q1 += y1 * y1;
            }
        }
        if (do_stats) {
            #pragma unroll
            for (int m = 4; m <= 16; m <<= 1) {
                s0 += __shfl_xor_sync(0xffffffffu, s0, m);
                s1 += __shfl_xor_sync(0xffffffffu, s1, m);
                q0 += __shfl_xor_sync(0xffffffffu, q0, m);
                q1 += __shfl_xor_sync(0xffffffffu, q1, m);
            }
            if (g == 0) {
                atomicAdd(&g_sum[soff + col], s0);
                atomicAdd(&g_sum[soff + col + 1], s1);
                atomicAdd(&g_ssq[soff + col], q0);
                atomicAdd(&g_ssq[soff + col + 1], q1);
            }
        }
    }
}

// ---------------- decoder (fp32) ----------------------------------------------------
__global__ void decoder_kernel(const int* __restrict__ ls, const int* __restrict__ ld,
                               float* __restrict__ out, int n) {
    int e = (blockIdx.x * blockDim.x + threadIdx.x) >> 5;
    int lane = threadIdx.x & 31;
    if (e >= n) return;
    int a = ls[e], b = ld[e];
    float4 u = *(const float4*)(g_g2 + (size_t)a * HD + lane * 4);
    float4 v = *(const float4*)(g_d2 + (size_t)b * HD + lane * 4);
    float p = u.x * v.x + u.y * v.y + u.z * v.z + u.w * v.w;
    #pragma unroll
    for (int off = 16; off > 0; off >>= 1)
        p += __shfl_xor_sync(0xffffffffu, p, off);
    if (lane == 0) out[e] = p;
}

// ---------------- launch ------------------------------------------------------------
extern "C" void kernel_launch(void* const* d_in, const int* in_sizes, int n_in,
                              void* d_out, int out_size) {
    const float* x_gene  = (const float*)d_in[0];
    const float* x_dis   = (const float*)d_in[1];
    const float* W_dst1  = (const float*)d_in[2];
    const float* W_src1  = (const float*)d_in[3];
    const float* W_upd1  = (const float*)d_in[4];
    const float* b_dst1  = (const float*)d_in[5];
    const float* b_src1  = (const float*)d_in[6];
    const float* b_upd1  = (const float*)d_in[7];
    const float* W_dst2  = (const float*)d_in[8];
    const float* W_src2  = (const float*)d_in[9];
    const float* W_upd2  = (const float*)d_in[10];
    const float* b_dst2  = (const float*)d_in[11];
    const float* b_src2  = (const float*)d_in[12];
    const float* b_upd2  = (const float*)d_in[13];
    const float* bn_gamma = (const float*)d_in[14];
    const float* bn_beta  = (const float*)d_in[15];
    const int* gg_src  = (const int*)d_in[16];
    const int* gg_dst  = (const int*)d_in[17];
    const int* gda_src = (const int*)d_in[18];
    const int* gda_dst = (const int*)d_in[19];
    const int* label_src = (const int*)d_in[20];
    const int* label_dst = (const int*)d_in[21];
    float* out = (float*)d_out;

    cudaFuncSetAttribute(gemm_async_kernel, cudaFuncAttributeMaxDynamicSharedMemorySize, GEMM_SMEM);

    // side stream + events (created once, outside capture)
    static cudaStream_t s1 = nullptr;
    static cudaEvent_t evFork = nullptr, evJoinP = nullptr, evCsr = nullptr;
    static cudaEvent_t evD0 = nullptr, evMid = nullptr, evD1 = nullptr;
    if (!s1) {
        cudaStreamCreate(&s1);
        cudaEventCreateWithFlags(&evFork, cudaEventDisableTiming);
        cudaEventCreateWithFlags(&evJoinP, cudaEventDisableTiming);
        cudaEventCreateWithFlags(&evCsr, cudaEventDisableTiming);
        cudaEventCreateWithFlags(&evD0, cudaEventDisableTiming);
        cudaEventCreateWithFlags(&evMid, cudaEventDisableTiming);
        cudaEventCreateWithFlags(&evD1, cudaEventDisableTiming);
    }

    void *p_cnt_gg, *p_cnt_rev, *p_cnt_gda, *p_sum, *p_ssq;
    cudaGetSymbolAddress(&p_cnt_gg, g_cnt_gg);
    cudaGetSymbolAddress(&p_cnt_rev, g_cnt_rev);
    cudaGetSymbolAddress(&p_cnt_gda, g_cnt_gda);
    cudaGetSymbolAddress(&p_sum, g_sum);
    cudaGetSymbolAddress(&p_ssq, g_ssq);

    const int nblkG = (NGn + 127) / 128;
    const int nblkD = (NDn + 127) / 128;
    const int aggGBlk = (2 * NGn * 32 + 255) / 256;
    const int aggDBlk = (NDn * 32 + 255) / 256;

    // ---- prologue fork: side chain = tohalf + weight prep ----
    cudaEventRecord(evFork, 0);
    cudaStreamWaitEvent(s1, evFork, 0);
    tohalf_kernel<<<2048, 256, 0, s1>>>(x_gene, x_dis);
    wprep_kernel<<<54, 256, 0, s1>>>(W_dst1, W_src1, W_upd1, W_dst2, W_src2, W_upd2,
                                     b_dst1, b_src1, b_upd1, b_dst2, b_src2, b_upd2);
    wcombine_kernel<<<(2 * HD * HD + 255) / 256, 256, 0, s1>>>();
    cudaEventRecord(evJoinP, s1);

    // ---- main chain: zeroing + CSR build ----
    cudaMemsetAsync(p_cnt_gg, 0, NGn * sizeof(int));
    cudaMemsetAsync(p_cnt_rev, 0, NGn * sizeof(int));
    cudaMemsetAsync(p_cnt_gda, 0, NDn * sizeof(int));
    cudaMemsetAsync(p_sum, 0, 2 * HD * sizeof(float));
    cudaMemsetAsync(p_ssq, 0, 2 * HD * sizeof(float));
    hist_all_kernel<<<4096, 256>>>(gg_dst, gda_src, gda_dst);
    scan_phase1<<<NBTOT, 256>>>();
    scan_phase3<<<NBTOT, 256>>>();
    fill_all_kernel<<<4096, 256>>>(gg_src, gg_dst, gda_src, gda_dst);
    cudaEventRecord(evCsr, 0);

    // main needs the side prologue (tohalf + weights) before layer work
    cudaStreamWaitEvent(0, evJoinP, 0);
    // side (already past its prologue) needs CSR before aggD
    cudaStreamWaitEvent(s1, evCsr, 0);

    // ---- layer 0: gene chain on main, disease chain on side ----
    agg_all_kernel<<<aggGBlk, 256>>>(0, 0, 2 * NGn);
    gemm_async_kernel<<<nblkG, 256, GEMM_SMEM>>>(x_gene, x_dis, 0, 1);
    agg_all_kernel<<<aggDBlk, 256, 0, s1>>>(0, 2 * NGn, NDn);
    gemm_async_kernel<<<nblkD, 256, GEMM_SMEM, s1>>>(x_gene, x_dis, 0, 0);
    cudaEventRecord(evD0, s1);

    // join: bnfinal needs stats from BOTH gemms
    cudaStreamWaitEvent(0, evD0, 0);
    bnfinal_kernel<<<1, 256>>>(bn_gamma, bn_beta);
    cudaEventRecord(evMid, 0);
    cudaStreamWaitEvent(s1, evMid, 0);

    // ---- layer 1 ----
    agg_all_kernel<<<aggGBlk, 256>>>(1, 0, 2 * NGn);
    gemm_async_kernel<<<nblkG, 256, GEMM_SMEM>>>(x_gene, x_dis, 1, 1);
    agg_all_kernel<<<aggDBlk, 256, 0, s1>>>(1, 2 * NGn, NDn);
    gemm_async_kernel<<<nblkD, 256, GEMM_SMEM, s1>>>(x_gene, x_dis, 1, 0);
    cudaEventRecord(evD1, s1);

    // join for decoder (needs g2 + d2)
    cudaStreamWaitEvent(0, evD1, 0);
    decoder_kernel<<<(ELABn * 32 + 255) / 256, 256>>>(label_src, label_dst, out, ELABn);
}